// round 1
// baseline (speedup 1.0000x reference)
#include <cuda_runtime.h>
#include <math.h>
#include <stdint.h>

// Problem constants
#define NPTS (4096 * 64)      // total sample points
#define NRAYS 4096
#define SPP 64                // samples per ray
#define HASH_T 2097152u       // 1<<21
#define HASH_MASK 2097151u
#define P1H 2654435761u
#define P2H 805459861u

// Scratch: transposed bottleneck [256][NPTS]  (256 MB device global — allowed)
__device__ float g_bottT[256 * (size_t)NPTS];

// ---------------------------------------------------------------------------
// Kernel A: contract + hash-grid encode + MLP1 (40 -> 64 relu -> 256)
// one thread per point; weights cached in dynamic smem
// smem layout (floats): w1[2560] w2[16384] b1[64] b2[256]  = 19264 floats
// ---------------------------------------------------------------------------
__global__ void __launch_bounds__(256) kernA(
    const float* __restrict__ coords,
    const float4* __restrict__ emb,
    const float* __restrict__ w1, const float* __restrict__ b1,
    const float* __restrict__ w2, const float* __restrict__ b2,
    float* __restrict__ density, float* __restrict__ bottT)
{
    extern __shared__ float sm[];
    float* s_w1 = sm;                 // [40][64]
    float* s_w2 = sm + 2560;          // [64][256]
    float* s_b1 = sm + 2560 + 16384;  // [64]
    float* s_b2 = s_b1 + 64;          // [256]

    const int t = threadIdx.x;
    for (int i = t; i < 2560; i += 256)  s_w1[i] = w1[i];
    for (int i = t; i < 16384; i += 256) s_w2[i] = w2[i];
    if (t < 64) s_b1[t] = b1[t];
    if (t < 256) s_b2[t] = b2[t];
    __syncthreads();

    const int pid = blockIdx.x * 256 + t;

    float cx = coords[pid * 3 + 0];
    float cy = coords[pid * 3 + 1];
    float cz = coords[pid * 3 + 2];

    // multinerf contraction
    float nn = sqrtf(cx * cx + cy * cy + cz * cz);
    nn = fmaxf(nn, 1.1920929e-7f);
    if (nn > 1.0f) {
        float sc = 2.0f - 1.0f / nn;
        cx = sc * (cx / nn);
        cy = sc * (cy / nn);
        cz = sc * (cz / nn);
    }
    // /bound(2), then to [0,1]
    cx *= 0.5f; cy *= 0.5f; cz *= 0.5f;
    const float ux = (cx + 1.0f) * 0.5f;
    const float uy = (cy + 1.0f) * 0.5f;
    const float uz = (cz + 1.0f) * 0.5f;

    const int offs[10] = {0, 4096, 36864, 299008, 2396160,
                          4493312, 6590464, 8687616, 10784768, 12881920};

    float f[40];
#pragma unroll
    for (int i = 0; i < 40; i++) f[i] = 0.0f;

#pragma unroll
    for (int l = 0; l < 10; l++) {
        const int res = 16 << l;
        const float s = (float)res - 1.0f;
        float px = ux * s + 0.5f;
        float py = uy * s + 0.5f;
        float pz = uz * s + 0.5f;
        float gxf = floorf(px), gyf = floorf(py), gzf = floorf(pz);
        float fx = px - gxf, fy = py - gyf, fz = pz - gzf;
        int gx = (int)gxf, gy = (int)gyf, gz = (int)gzf;
#pragma unroll
        for (int c = 0; c < 8; c++) {
            const int b0 = c & 1, b1c = (c >> 1) & 1, b2c = (c >> 2) & 1;
            float w = (b0 ? fx : 1.0f - fx) * (b1c ? fy : 1.0f - fy)
                    * (b2c ? fz : 1.0f - fz);
            int idx;
            if (l < 4) {
                idx = (gx + b0) + (gy + b1c) * res + (gz + b2c) * res * res;
            } else {
                idx = (int)(((uint32_t)(gx + b0)
                           ^ ((uint32_t)(gy + b1c) * P1H)
                           ^ ((uint32_t)(gz + b2c) * P2H)) & HASH_MASK);
            }
            float4 e = __ldg(&emb[offs[l] + idx]);
            f[l * 4 + 0] += w * e.x;
            f[l * 4 + 1] += w * e.y;
            f[l * 4 + 2] += w * e.z;
            f[l * 4 + 3] += w * e.w;
        }
    }

    // h = relu(f @ w1 + b1)   (40 -> 64)
    float h[64];
#pragma unroll
    for (int j4 = 0; j4 < 16; j4++) {
        float4 a = *(const float4*)&s_b1[j4 * 4];
#pragma unroll
        for (int k = 0; k < 40; k++) {
            float4 wv = *(const float4*)&s_w1[k * 64 + j4 * 4];
            a.x += f[k] * wv.x;
            a.y += f[k] * wv.y;
            a.z += f[k] * wv.z;
            a.w += f[k] * wv.w;
        }
        h[j4 * 4 + 0] = fmaxf(a.x, 0.0f);
        h[j4 * 4 + 1] = fmaxf(a.y, 0.0f);
        h[j4 * 4 + 2] = fmaxf(a.z, 0.0f);
        h[j4 * 4 + 3] = fmaxf(a.w, 0.0f);
    }

    // bott = h @ w2 + b2  (64 -> 256), stored transposed; density = softplus(bott0 - 1)
    for (int n4 = 0; n4 < 64; n4++) {
        float4 a = *(const float4*)&s_b2[n4 * 4];
#pragma unroll
        for (int j = 0; j < 64; j++) {
            float4 wv = *(const float4*)&s_w2[j * 256 + n4 * 4];
            a.x += h[j] * wv.x;
            a.y += h[j] * wv.y;
            a.z += h[j] * wv.z;
            a.w += h[j] * wv.w;
        }
        const int n = n4 * 4;
        bottT[(size_t)(n + 0) * NPTS + pid] = a.x;
        bottT[(size_t)(n + 1) * NPTS + pid] = a.y;
        bottT[(size_t)(n + 2) * NPTS + pid] = a.z;
        bottT[(size_t)(n + 3) * NPTS + pid] = a.w;
        if (n4 == 0) {
            float r = a.x - 1.0f;  // DENSITY_BIAS
            float d = (r > 0.0f) ? (r + log1pf(expf(-r))) : log1pf(expf(r));
            density[pid] = d;
        }
    }
}

// ---------------------------------------------------------------------------
// Kernel B: per-ray block (64 samples), two fused GEMMs + rgb head
// s_act rows: [0..255] = x (GEMM1 output), [256..511] = bottleneck,
//             [512..538] = dir enc, [539..543] = zero pad
// ---------------------------------------------------------------------------
#define SACT_ROWS 544
#define SACT_FLOATS (SACT_ROWS * 64)
#define SW_FLOATS 2048
#define SRED_FLOATS (16 * 64 * 3)
#define SMEMB_FLOATS (SACT_FLOATS + SW_FLOATS + SRED_FLOATS)

__global__ void __launch_bounds__(256) kernB(
    const float* __restrict__ bottT,
    const float* __restrict__ viewdirs,
    const float* __restrict__ lin0_w, const float* __restrict__ lin0_b,
    const float* __restrict__ lin1_w, const float* __restrict__ lin1_b,
    const float* __restrict__ rgb_w,  const float* __restrict__ rgb_b,
    float* __restrict__ out_rgb)
{
    extern __shared__ float sm[];
    float* s_act = sm;                    // [544][64]
    float* s_w   = sm + SACT_FLOATS;      // [8][256]
    float* s_red = s_w + SW_FLOATS;       // [16][64][3]

    const int t = threadIdx.x;
    const int ray = blockIdx.x;
    const int base = ray * SPP;

    // bottleneck rows 256..511 (coalesced rows of bottT)
    for (int idx = t; idx < 256 * 64; idx += 256) {
        int k = idx >> 6, m = idx & 63;
        s_act[(256 + k) * 64 + m] = bottT[(size_t)k * NPTS + base + m];
    }
    // dir encoding rows 512..538 (broadcast per ray)
    if (t < 27) {
        float dx = viewdirs[ray * 3 + 0];
        float dy = viewdirs[ray * 3 + 1];
        float dz = viewdirs[ray * 3 + 2];
        float v;
        if (t < 3) {
            v = (t == 0) ? dx : ((t == 1) ? dy : dz);
        } else {
            int idx = t - 3;
            int deg = idx / 6;
            int rem = idx % 6;
            float d = ((rem % 3) == 0) ? dx : (((rem % 3) == 1) ? dy : dz);
            float xb = d * (float)(1 << deg);
            v = (rem < 3) ? sinf(xb) : sinf(xb + 1.5707964f);
        }
        for (int m = 0; m < 64; m++) s_act[(512 + t) * 64 + m] = v;
    }
    // zero pad rows 539..543
    for (int idx = t; idx < 5 * 64; idx += 256) s_act[539 * 64 + idx] = 0.0f;
    __syncthreads();

    const int mt = t & 15, nt = t >> 4;
    const int m0 = mt * 4, n0 = nt * 16;

    // ---------------- GEMM1: x = relu(inp @ lin0_w + b), K = 283 -------------
    float acc[4][16];
#pragma unroll
    for (int j = 0; j < 16; j++) {
        float bb = __ldg(&lin0_b[n0 + j]);
        acc[0][j] = bb; acc[1][j] = bb; acc[2][j] = bb; acc[3][j] = bb;
    }
    for (int kc = 0; kc < 283; kc += 8) {
        __syncthreads();
        for (int i = t; i < 2048; i += 256) {
            int kk = kc + (i >> 8), col = i & 255;
            s_w[i] = (kk < 283) ? lin0_w[kk * 256 + col] : 0.0f;
        }
        __syncthreads();
#pragma unroll
        for (int ck = 0; ck < 8; ck++) {
            float4 a = *(const float4*)&s_act[(256 + kc + ck) * 64 + m0];
            float av[4] = {a.x, a.y, a.z, a.w};
#pragma unroll
            for (int j4 = 0; j4 < 4; j4++) {
                float4 b = *(const float4*)&s_w[ck * 256 + n0 + j4 * 4];
                float bv[4] = {b.x, b.y, b.z, b.w};
#pragma unroll
                for (int mi = 0; mi < 4; mi++)
#pragma unroll
                    for (int bj = 0; bj < 4; bj++)
                        acc[mi][j4 * 4 + bj] += av[mi] * bv[bj];
            }
        }
    }
    __syncthreads();
    // write relu(x) into rows 0..255
#pragma unroll
    for (int j = 0; j < 16; j++) {
        float4 v;
        v.x = fmaxf(acc[0][j], 0.0f);
        v.y = fmaxf(acc[1][j], 0.0f);
        v.z = fmaxf(acc[2][j], 0.0f);
        v.w = fmaxf(acc[3][j], 0.0f);
        *(float4*)&s_act[(n0 + j) * 64 + m0] = v;
    }
    __syncthreads();

    // ---------------- GEMM2: y = relu(concat @ lin1_w + b), K = 539 ----------
    float acc2[4][16];
#pragma unroll
    for (int j = 0; j < 16; j++) {
        float bb = __ldg(&lin1_b[n0 + j]);
        acc2[0][j] = bb; acc2[1][j] = bb; acc2[2][j] = bb; acc2[3][j] = bb;
    }
    for (int kc = 0; kc < 539; kc += 8) {
        __syncthreads();
        for (int i = t; i < 2048; i += 256) {
            int kk = kc + (i >> 8), col = i & 255;
            s_w[i] = (kk < 539) ? lin1_w[kk * 256 + col] : 0.0f;
        }
        __syncthreads();
#pragma unroll
        for (int ck = 0; ck < 8; ck++) {
            float4 a = *(const float4*)&s_act[(kc + ck) * 64 + m0];
            float av[4] = {a.x, a.y, a.z, a.w};
#pragma unroll
            for (int j4 = 0; j4 < 4; j4++) {
                float4 b = *(const float4*)&s_w[ck * 256 + n0 + j4 * 4];
                float bv[4] = {b.x, b.y, b.z, b.w};
#pragma unroll
                for (int mi = 0; mi < 4; mi++)
#pragma unroll
                    for (int bj = 0; bj < 4; bj++)
                        acc2[mi][j4 * 4 + bj] += av[mi] * bv[bj];
            }
        }
    }

    // ---------------- rgb head: y(relu) @ rgb_w, partial reduce over nt ------
    float p[4][3];
#pragma unroll
    for (int mi = 0; mi < 4; mi++) { p[mi][0] = 0; p[mi][1] = 0; p[mi][2] = 0; }
#pragma unroll
    for (int j = 0; j < 16; j++) {
        int n = n0 + j;
        float r0 = __ldg(&rgb_w[n * 3 + 0]);
        float r1 = __ldg(&rgb_w[n * 3 + 1]);
        float r2 = __ldg(&rgb_w[n * 3 + 2]);
#pragma unroll
        for (int mi = 0; mi < 4; mi++) {
            float xv = fmaxf(acc2[mi][j], 0.0f);
            p[mi][0] += xv * r0;
            p[mi][1] += xv * r1;
            p[mi][2] += xv * r2;
        }
    }
    __syncthreads();  // s_red region reuse safety (after all prior phases)
#pragma unroll
    for (int mi = 0; mi < 4; mi++) {
        s_red[(nt * 64 + m0 + mi) * 3 + 0] = p[mi][0];
        s_red[(nt * 64 + m0 + mi) * 3 + 1] = p[mi][1];
        s_red[(nt * 64 + m0 + mi) * 3 + 2] = p[mi][2];
    }
    __syncthreads();
    if (t < 192) {
        int m = t / 3;
        int c = t - m * 3;
        float v = 0.0f;
#pragma unroll
        for (int g = 0; g < 16; g++) v += s_red[(g * 64 + m) * 3 + c];
        v += __ldg(&rgb_b[c]);
        float sg = 1.0f / (1.0f + expf(-v));
        out_rgb[(size_t)(base + m) * 3 + c] = sg * 1.002f - 0.001f;
    }
}

// ---------------------------------------------------------------------------
extern "C" void kernel_launch(void* const* d_in, const int* in_sizes, int n_in,
                              void* d_out, int out_size)
{
    const float*  coords   = (const float*)d_in[0];
    // d_in[1] = radius (unused by reference)
    const float*  viewdirs = (const float*)d_in[2];
    const float4* emb      = (const float4*)d_in[3];
    const float*  w1       = (const float*)d_in[4];
    const float*  b1       = (const float*)d_in[5];
    const float*  w2       = (const float*)d_in[6];
    const float*  b2       = (const float*)d_in[7];
    const float*  lin0_w   = (const float*)d_in[8];
    const float*  lin0_b   = (const float*)d_in[9];
    const float*  lin1_w   = (const float*)d_in[10];
    const float*  lin1_b   = (const float*)d_in[11];
    const float*  rgb_w    = (const float*)d_in[12];
    const float*  rgb_b    = (const float*)d_in[13];

    float* dout    = (float*)d_out;
    float* density = dout;            // [NPTS]
    float* rgb     = dout + NPTS;     // [NPTS][3]

    float* bottT = nullptr;
    cudaGetSymbolAddress((void**)&bottT, g_bottT);

    const size_t smemA = 19264 * sizeof(float);
    const size_t smemB = SMEMB_FLOATS * sizeof(float);
    cudaFuncSetAttribute(kernA, cudaFuncAttributeMaxDynamicSharedMemorySize,
                         (int)smemA);
    cudaFuncSetAttribute(kernB, cudaFuncAttributeMaxDynamicSharedMemorySize,
                         (int)smemB);

    kernA<<<NPTS / 256, 256, smemA>>>(coords, emb, w1, b1, w2, b2,
                                      density, bottT);
    kernB<<<NRAYS, 256, smemB>>>(bottT, viewdirs, lin0_w, lin0_b,
                                 lin1_w, lin1_b, rgb_w, rgb_b, rgb);
}

// round 3
// speedup vs baseline: 3.0262x; 3.0262x over previous
#include <cuda_runtime.h>
#include <math.h>
#include <stdint.h>

// ---------------------------------------------------------------- constants
#define NPTS (4096 * 64)
#define NRAYS 4096
#define HASH_MASK 2097151u
#define P1H 2654435761u
#define P2H 805459861u

#define TILE_M 128
#define NTILES (NPTS / TILE_M)   // 2048
#define K1 288                    // 283 padded

// kernB chunk schedule: 18 (gemm1) + 16 (gemm2 x-part) + 18 (gemm2 inp-part)
#define NCHUNK 52

// smem layout (bytes)
#define XSTR 260
#define X_BYTES (128 * XSTR * 4)            // 133120
#define A_SM_OFF X_BYTES
#define ABUF_B (128 * 20 * 4)               // 10240
#define W_SM_OFF (A_SM_OFF + 3 * ABUF_B)    // 163840
#define WBUF_B (256 * 20 * 4)               // 20480
#define BIAS_OFF (W_SM_OFF + 3 * WBUF_B)    // 225280
#define SMEMB_BYTES (BIAS_OFF + 5136)       // 230416

// ---------------------------------------------------------------- globals
__device__ float g_inp0[(size_t)NPTS * K1];  // [N,288] = [bott(256)|direnc(27)|0]
__device__ float g_W0T[256 * 288];           // lin0_w^T, tf32-rounded, zero-padded
__device__ float g_W1T[256 * 544];           // lin1_w^T, tf32-rounded, zero-padded

// ---------------------------------------------------------------- helpers
__device__ __forceinline__ float tf32r(float v) {
    uint32_t u;
    asm("cvt.rna.tf32.f32 %0, %1;" : "=r"(u) : "f"(v));
    return __uint_as_float(u);
}
__device__ __forceinline__ void mma_tf32(float c[4],
    uint32_t a0, uint32_t a1, uint32_t a2, uint32_t a3,
    uint32_t b0, uint32_t b1)
{
    asm volatile(
        "mma.sync.aligned.m16n8k8.row.col.f32.tf32.tf32.f32 "
        "{%0,%1,%2,%3},{%4,%5,%6,%7},{%8,%9},{%0,%1,%2,%3};"
        : "+f"(c[0]), "+f"(c[1]), "+f"(c[2]), "+f"(c[3])
        : "r"(a0), "r"(a1), "r"(a2), "r"(a3), "r"(b0), "r"(b1));
}
__device__ __forceinline__ uint32_t smem_u32(const void* p) {
    uint32_t a;
    asm("{ .reg .u64 t; cvta.to.shared.u64 t, %1; cvt.u32.u64 %0, t; }"
        : "=r"(a) : "l"(p));
    return a;
}
#define CP16(d, s) asm volatile("cp.async.cg.shared.global [%0], [%1], 16;" :: "r"(d), "l"(s))
#define CPCOMMIT() asm volatile("cp.async.commit_group;")
#define CPWAIT2()  asm volatile("cp.async.wait_group 2;" ::: "memory")

// ---------------------------------------------------------------- prepW
__global__ void __launch_bounds__(256) prepW(
    const float* __restrict__ l0, const float* __restrict__ l1,
    float* __restrict__ W0T, float* __restrict__ W1T)
{
    int idx = blockIdx.x * 256 + threadIdx.x;
    if (idx < 256 * 288) {
        int n = idx / 288, k = idx % 288;
        W0T[idx] = (k < 283) ? tf32r(l0[k * 256 + n]) : 0.0f;
    }
    if (idx < 256 * 544) {
        int n = idx / 544, k = idx % 544;
        W1T[idx] = (k < 539) ? tf32r(l1[k * 256 + n]) : 0.0f;
    }
}

// ---------------------------------------------------------------- kernel A
__global__ void __launch_bounds__(256) kernA(
    const float* __restrict__ coords,
    const float* __restrict__ viewdirs,
    const float4* __restrict__ emb,
    const float* __restrict__ w1, const float* __restrict__ b1,
    const float* __restrict__ w2, const float* __restrict__ b2,
    float* __restrict__ density, float* __restrict__ inp0)
{
    extern __shared__ float sm[];
    float* s_w1 = sm;                 // [40][64]
    float* s_w2 = sm + 2560;          // [64][256]
    float* s_b1 = sm + 2560 + 16384;
    float* s_b2 = s_b1 + 64;

    const int t = threadIdx.x;
    for (int i = t; i < 2560; i += 256)  s_w1[i] = w1[i];
    for (int i = t; i < 16384; i += 256) s_w2[i] = w2[i];
    if (t < 64)  s_b1[t] = b1[t];
    if (t < 256) s_b2[t] = b2[t];
    __syncthreads();

    const int pid = blockIdx.x * 256 + t;

    float cx = coords[pid * 3 + 0];
    float cy = coords[pid * 3 + 1];
    float cz = coords[pid * 3 + 2];
    float nn = sqrtf(cx * cx + cy * cy + cz * cz);
    nn = fmaxf(nn, 1.1920929e-7f);
    if (nn > 1.0f) {
        float sc = 2.0f - 1.0f / nn;
        cx = sc * (cx / nn); cy = sc * (cy / nn); cz = sc * (cz / nn);
    }
    cx *= 0.5f; cy *= 0.5f; cz *= 0.5f;
    const float ux = (cx + 1.0f) * 0.5f;
    const float uy = (cy + 1.0f) * 0.5f;
    const float uz = (cz + 1.0f) * 0.5f;

    const int offs[10] = {0, 4096, 36864, 299008, 2396160,
                          4493312, 6590464, 8687616, 10784768, 12881920};
    float f[40];
#pragma unroll
    for (int i = 0; i < 40; i++) f[i] = 0.0f;

#pragma unroll
    for (int l = 0; l < 10; l++) {
        const int res = 16 << l;
        const float s = (float)res - 1.0f;
        float px = ux * s + 0.5f, py = uy * s + 0.5f, pz = uz * s + 0.5f;
        float gxf = floorf(px), gyf = floorf(py), gzf = floorf(pz);
        float fx = px - gxf, fy = py - gyf, fz = pz - gzf;
        int gx = (int)gxf, gy = (int)gyf, gz = (int)gzf;
#pragma unroll
        for (int c = 0; c < 8; c++) {
            const int b0 = c & 1, b1c = (c >> 1) & 1, b2c = (c >> 2) & 1;
            float w = (b0 ? fx : 1.0f - fx) * (b1c ? fy : 1.0f - fy)
                    * (b2c ? fz : 1.0f - fz);
            int idx;
            if (l < 4) {
                idx = (gx + b0) + (gy + b1c) * res + (gz + b2c) * res * res;
            } else {
                idx = (int)(((uint32_t)(gx + b0)
                           ^ ((uint32_t)(gy + b1c) * P1H)
                           ^ ((uint32_t)(gz + b2c) * P2H)) & HASH_MASK);
            }
            float4 e = __ldg(&emb[offs[l] + idx]);
            f[l * 4 + 0] += w * e.x; f[l * 4 + 1] += w * e.y;
            f[l * 4 + 2] += w * e.z; f[l * 4 + 3] += w * e.w;
        }
    }

    float h[64];
#pragma unroll
    for (int j4 = 0; j4 < 16; j4++) {
        float4 a = *(const float4*)&s_b1[j4 * 4];
#pragma unroll
        for (int k = 0; k < 40; k++) {
            float4 wv = *(const float4*)&s_w1[k * 64 + j4 * 4];
            a.x += f[k] * wv.x; a.y += f[k] * wv.y;
            a.z += f[k] * wv.z; a.w += f[k] * wv.w;
        }
        h[j4 * 4 + 0] = fmaxf(a.x, 0.0f); h[j4 * 4 + 1] = fmaxf(a.y, 0.0f);
        h[j4 * 4 + 2] = fmaxf(a.z, 0.0f); h[j4 * 4 + 3] = fmaxf(a.w, 0.0f);
    }

    float4* row4 = (float4*)(inp0 + (size_t)pid * K1);
    for (int n4 = 0; n4 < 64; n4++) {
        float4 a = *(const float4*)&s_b2[n4 * 4];
#pragma unroll
        for (int j = 0; j < 64; j++) {
            float4 wv = *(const float4*)&s_w2[j * 256 + n4 * 4];
            a.x += h[j] * wv.x; a.y += h[j] * wv.y;
            a.z += h[j] * wv.z; a.w += h[j] * wv.w;
        }
        if (n4 == 0) {
            float r = a.x - 1.0f;
            float d = (r > 0.0f) ? (r + log1pf(expf(-r))) : log1pf(expf(r));
            density[pid] = d;
        }
        row4[n4] = make_float4(tf32r(a.x), tf32r(a.y), tf32r(a.z), tf32r(a.w));
    }

    // dir encoding (27) + zero pad -> cols 256..287 (tf32-rounded)
    const int ray = pid >> 6;
    float dx = viewdirs[ray * 3 + 0];
    float dy = viewdirs[ray * 3 + 1];
    float dz = viewdirs[ray * 3 + 2];
    float de[32];
    de[0] = dx; de[1] = dy; de[2] = dz;
#pragma unroll
    for (int deg = 0; deg < 4; deg++) {
        float sc = (float)(1 << deg);
        float sx = dx * sc, sy = dy * sc, sz = dz * sc;
        de[3 + deg * 6 + 0] = sinf(sx); de[3 + deg * 6 + 1] = sinf(sy);
        de[3 + deg * 6 + 2] = sinf(sz); de[3 + deg * 6 + 3] = cosf(sx);
        de[3 + deg * 6 + 4] = cosf(sy); de[3 + deg * 6 + 5] = cosf(sz);
    }
#pragma unroll
    for (int i = 27; i < 32; i++) de[i] = 0.0f;
#pragma unroll
    for (int q = 0; q < 8; q++)
        row4[64 + q] = make_float4(tf32r(de[q * 4]), tf32r(de[q * 4 + 1]),
                                   tf32r(de[q * 4 + 2]), tf32r(de[q * 4 + 3]));
}

// ---------------------------------------------------------------- kernel B
// 256 threads, 8 warps: warp grid 2(M) x 4(N), warp tile 64x64, CTA tile 128x256
__device__ __forceinline__ void gemm_chunk(
    const float* __restrict__ As, int sa, int koff,
    const float* __restrict__ Ws,
    int m0, int n0w, int g, int t, float acc[4][8][4])
{
#pragma unroll
    for (int ks = 0; ks < 2; ks++) {
        const int kk = koff + ks * 8;
        uint32_t a[4][4], b[8][2];
#pragma unroll
        for (int mf = 0; mf < 4; mf++) {
            const int r0 = (m0 + mf * 16 + g) * sa + kk + t;
            a[mf][0] = __float_as_uint(As[r0]);
            a[mf][1] = __float_as_uint(As[r0 + 8 * sa]);
            a[mf][2] = __float_as_uint(As[r0 + 4]);
            a[mf][3] = __float_as_uint(As[r0 + 8 * sa + 4]);
        }
#pragma unroll
        for (int nf = 0; nf < 8; nf++) {
            const int rb = (n0w + nf * 8 + g) * 20 + ks * 8 + t;
            b[nf][0] = __float_as_uint(Ws[rb]);
            b[nf][1] = __float_as_uint(Ws[rb + 4]);
        }
#pragma unroll
        for (int mf = 0; mf < 4; mf++)
#pragma unroll
            for (int nf = 0; nf < 8; nf++)
                mma_tf32(acc[mf][nf], a[mf][0], a[mf][1], a[mf][2], a[mf][3],
                         b[nf][0], b[nf][1]);
    }
}

__global__ void __launch_bounds__(256, 1) kernB(
    const float* __restrict__ inp0,
    const float* __restrict__ W0T, const float* __restrict__ W1T,
    const float* __restrict__ b0g, const float* __restrict__ b1g,
    const float* __restrict__ rgbwg, const float* __restrict__ rgbbg,
    float* __restrict__ out_rgb)
{
    extern __shared__ char smem[];
    float* Xs = (float*)smem;                         // [128][260]
    float* s_b0 = (float*)(smem + BIAS_OFF);          // [256]
    float* s_b1 = (float*)(smem + BIAS_OFF + 1024);   // [256]
    float* s_rw = (float*)(smem + BIAS_OFF + 2048);   // [256][3]
    float* s_rb = (float*)(smem + BIAS_OFF + 5120);   // [3]
    const uint32_t sb = smem_u32(smem);

    const int t = threadIdx.x;
    const int wid = t >> 5, lane = t & 31;
    const int g = lane >> 2, tq = lane & 3;
    const int wm = wid & 1, wn = wid >> 1;
    const int m0 = wm * 64, n0w = wn * 64;
    const size_t base = (size_t)blockIdx.x * TILE_M;

    s_b0[t] = b0g[t];
    s_b1[t] = b1g[t];
    for (int i = t; i < 768; i += 256) s_rw[i] = rgbwg[i];
    if (t < 3) s_rb[t] = rgbbg[t];
    __syncthreads();

    // chunk loader
    auto issue_load = [&](int p) {
        const uint32_t abase = sb + A_SM_OFF + (uint32_t)(p % 3) * ABUF_B;
        const uint32_t wbase = sb + W_SM_OFF + (uint32_t)(p % 3) * WBUF_B;
        const float* wsrc; int wld, wcol, acol; bool hasA;
        if (p < 18)      { wsrc = W0T; wld = 288; wcol = p * 16; hasA = true;  acol = p * 16; }
        else if (p < 34) { wsrc = W1T; wld = 544; wcol = (p - 18) * 16; hasA = false; acol = 0; }
        else             { wsrc = W1T; wld = 544; wcol = 256 + (p - 34) * 16; hasA = true; acol = (p - 34) * 16; }
#pragma unroll
        for (int j = 0; j < 4; j++) {
            int i = t + 256 * j, row = i >> 2, seg = i & 3;
            CP16(wbase + (uint32_t)row * 80u + (uint32_t)seg * 16u,
                 wsrc + (size_t)row * wld + wcol + seg * 4);
        }
        if (hasA) {
#pragma unroll
            for (int j = 0; j < 2; j++) {
                int i = t + 256 * j, row = i >> 2, seg = i & 3;
                CP16(abase + (uint32_t)row * 80u + (uint32_t)seg * 16u,
                     inp0 + (base + (size_t)row) * K1 + acol + seg * 4);
            }
        }
    };

    float acc[4][8][4];
#pragma unroll
    for (int mf = 0; mf < 4; mf++)
#pragma unroll
        for (int nf = 0; nf < 8; nf++) {
            int col = n0w + nf * 8 + tq * 2;
            acc[mf][nf][0] = s_b0[col];
            acc[mf][nf][1] = s_b0[col + 1];
            acc[mf][nf][2] = s_b0[col];
            acc[mf][nf][3] = s_b0[col + 1];
        }

    issue_load(0); CPCOMMIT();
    issue_load(1); CPCOMMIT();
    issue_load(2); CPCOMMIT();

    for (int c = 0; c < NCHUNK; c++) {
        CPWAIT2();
        __syncthreads();

        const float* Ws = (const float*)(smem + W_SM_OFF + (c % 3) * WBUF_B);
        if (c >= 18 && c < 34) {
            gemm_chunk(Xs, XSTR, (c - 18) * 16, Ws, m0, n0w, g, tq, acc);
        } else {
            const float* As = (const float*)(smem + A_SM_OFF + (c % 3) * ABUF_B);
            gemm_chunk(As, 20, 0, Ws, m0, n0w, g, tq, acc);
        }

        if (c == 17) {
            // epilogue 1: relu(x + b0) -> tf32 -> X panel; reset acc to b1
#pragma unroll
            for (int mf = 0; mf < 4; mf++) {
                const int r0 = m0 + mf * 16 + g;
#pragma unroll
                for (int nf = 0; nf < 8; nf++) {
                    const int col = n0w + nf * 8 + tq * 2;
                    Xs[r0 * XSTR + col]       = tf32r(fmaxf(acc[mf][nf][0], 0.0f));
                    Xs[r0 * XSTR + col + 1]   = tf32r(fmaxf(acc[mf][nf][1], 0.0f));
                    Xs[(r0+8) * XSTR + col]   = tf32r(fmaxf(acc[mf][nf][2], 0.0f));
                    Xs[(r0+8) * XSTR + col+1] = tf32r(fmaxf(acc[mf][nf][3], 0.0f));
                    acc[mf][nf][0] = s_b1[col];
                    acc[mf][nf][1] = s_b1[col + 1];
                    acc[mf][nf][2] = s_b1[col];
                    acc[mf][nf][3] = s_b1[col + 1];
                }
            }
        }
        __syncthreads();
        if (c + 3 < NCHUNK) issue_load(c + 3);
        CPCOMMIT();
    }

    // ---------------- rgb head ----------------
    float p[8][3];
#pragma unroll
    for (int r = 0; r < 8; r++) { p[r][0] = 0; p[r][1] = 0; p[r][2] = 0; }
#pragma unroll
    for (int mf = 0; mf < 4; mf++)
#pragma unroll
        for (int nf = 0; nf < 8; nf++) {
            const int col0 = n0w + nf * 8 + tq * 2, col1 = col0 + 1;
            float y00 = fmaxf(acc[mf][nf][0], 0.0f);
            float y01 = fmaxf(acc[mf][nf][1], 0.0f);
            float y10 = fmaxf(acc[mf][nf][2], 0.0f);
            float y11 = fmaxf(acc[mf][nf][3], 0.0f);
#pragma unroll
            for (int ch = 0; ch < 3; ch++) {
                float w0 = s_rw[col0 * 3 + ch], w1 = s_rw[col1 * 3 + ch];
                p[mf * 2 + 0][ch] += y00 * w0 + y01 * w1;
                p[mf * 2 + 1][ch] += y10 * w0 + y11 * w1;
            }
        }
    // reduce over the 4 lanes of a t-group
#pragma unroll
    for (int r = 0; r < 8; r++)
#pragma unroll
        for (int ch = 0; ch < 3; ch++) {
            p[r][ch] += __shfl_xor_sync(0xffffffffu, p[r][ch], 1);
            p[r][ch] += __shfl_xor_sync(0xffffffffu, p[r][ch], 2);
        }

    float* part = (float*)(smem + A_SM_OFF);  // [4 wn][128 rows][3]
    __syncthreads();   // all computes done; safe to reuse A buffers
    if (tq == 0) {
#pragma unroll
        for (int mf = 0; mf < 4; mf++)
#pragma unroll
            for (int h = 0; h < 2; h++) {
                int row = m0 + mf * 16 + g + 8 * h;
                int r = mf * 2 + h;
                part[(wn * 128 + row) * 3 + 0] = p[r][0];
                part[(wn * 128 + row) * 3 + 1] = p[r][1];
                part[(wn * 128 + row) * 3 + 2] = p[r][2];
            }
    }
    __syncthreads();
    if (t < 128) {
        const size_t gidx = base + t;
#pragma unroll
        for (int ch = 0; ch < 3; ch++) {
            float v = part[(0 * 128 + t) * 3 + ch] + part[(1 * 128 + t) * 3 + ch]
                    + part[(2 * 128 + t) * 3 + ch] + part[(3 * 128 + t) * 3 + ch]
                    + s_rb[ch];
            float sg = 1.0f / (1.0f + expf(-v));
            out_rgb[gidx * 3 + ch] = sg * 1.002f - 0.001f;
        }
    }
}

// ---------------------------------------------------------------- launch
extern "C" void kernel_launch(void* const* d_in, const int* in_sizes, int n_in,
                              void* d_out, int out_size)
{
    const float*  coords   = (const float*)d_in[0];
    const float*  viewdirs = (const float*)d_in[2];
    const float4* emb      = (const float4*)d_in[3];
    const float*  w1       = (const float*)d_in[4];
    const float*  b1       = (const float*)d_in[5];
    const float*  w2       = (const float*)d_in[6];
    const float*  b2       = (const float*)d_in[7];
    const float*  lin0_w   = (const float*)d_in[8];
    const float*  lin0_b   = (const float*)d_in[9];
    const float*  lin1_w   = (const float*)d_in[10];
    const float*  lin1_b   = (const float*)d_in[11];
    const float*  rgb_w    = (const float*)d_in[12];
    const float*  rgb_b    = (const float*)d_in[13];

    float* dout    = (float*)d_out;
    float* density = dout;
    float* rgb     = dout + NPTS;

    float *inp0, *W0T, *W1T;
    cudaGetSymbolAddress((void**)&inp0, g_inp0);
    cudaGetSymbolAddress((void**)&W0T, g_W0T);
    cudaGetSymbolAddress((void**)&W1T, g_W1T);

    const size_t smemA = 19264 * sizeof(float);
    cudaFuncSetAttribute(kernA, cudaFuncAttributeMaxDynamicSharedMemorySize, (int)smemA);
    cudaFuncSetAttribute(kernB, cudaFuncAttributeMaxDynamicSharedMemorySize, SMEMB_BYTES);

    prepW<<<544, 256>>>(lin0_w, lin1_w, W0T, W1T);
    kernA<<<NPTS / 256, 256, smemA>>>(coords, viewdirs, emb, w1, b1, w2, b2,
                                      density, inp0);
    kernB<<<NTILES, 256, SMEMB_BYTES>>>(inp0, W0T, W1T, lin0_b, lin1_b,
                                        rgb_w, rgb_b, rgb);
}

// round 4
// speedup vs baseline: 3.9641x; 1.3099x over previous
#include <cuda_runtime.h>
#include <math.h>
#include <stdint.h>

// ---------------------------------------------------------------- constants
#define NPTS (4096 * 64)
#define NRAYS 4096
#define HASH_MASK 2097151u
#define P1H 2654435761u
#define P2H 805459861u

#define TILE_M 128
#define NTILES (NPTS / TILE_M)   // 2048
#define K1 288                    // 283 padded

// kernB chunk schedule: 18 (gemm1) + 16 (gemm2 x-part) + 18 (gemm2 inp-part)
#define NCHUNK 52

// kernB smem layout (bytes)
#define XSTR 260
#define X_BYTES (128 * XSTR * 4)            // 133120
#define A_SM_OFF X_BYTES
#define ABUF_B (128 * 20 * 4)               // 10240
#define W_SM_OFF (A_SM_OFF + 3 * ABUF_B)    // 163840
#define WBUF_B (256 * 20 * 4)               // 20480
#define BIAS_OFF (W_SM_OFF + 3 * WBUF_B)    // 225280
#define SMEMB_BYTES (BIAS_OFF + 5136)       // 230416

// kernM smem layout (floats)
#define M_FEATS 0                 // [128][52]
#define M_H     (128 * 52)        // [128][68]
#define M_U1    (M_H + 128 * 68)  // [64][52]
#define M_U2    (M_U1 + 64 * 52)  // [256][68]
#define M_B1    (M_U2 + 256 * 68)
#define M_B2    (M_B1 + 64)
#define M_DE    (M_B2 + 256)      // [2][32]
#define SMEMM_FLOATS (M_DE + 64)
#define SMEMM_BYTES (SMEMM_FLOATS * 4)

// ---------------------------------------------------------------- globals
__device__ float g_feats[(size_t)NPTS * 40];
__device__ float g_inp0[(size_t)NPTS * K1];  // [N,288] = [bott(256)|direnc(27)|0]
__device__ float g_W0T[256 * 288];           // lin0_w^T (tf32, padded)
__device__ float g_W1T[256 * 544];           // lin1_w^T (tf32, padded)
__device__ float g_U1T[64 * 40];             // w1^T (tf32)
__device__ float g_U2T[256 * 64];            // w2^T (tf32)

// ---------------------------------------------------------------- helpers
__device__ __forceinline__ float tf32r(float v) {
    uint32_t u;
    asm("cvt.rna.tf32.f32 %0, %1;" : "=r"(u) : "f"(v));
    return __uint_as_float(u);
}
__device__ __forceinline__ void mma_tf32(float c[4],
    uint32_t a0, uint32_t a1, uint32_t a2, uint32_t a3,
    uint32_t b0, uint32_t b1)
{
    asm volatile(
        "mma.sync.aligned.m16n8k8.row.col.f32.tf32.tf32.f32 "
        "{%0,%1,%2,%3},{%4,%5,%6,%7},{%8,%9},{%0,%1,%2,%3};"
        : "+f"(c[0]), "+f"(c[1]), "+f"(c[2]), "+f"(c[3])
        : "r"(a0), "r"(a1), "r"(a2), "r"(a3), "r"(b0), "r"(b1));
}
__device__ __forceinline__ uint32_t smem_u32(const void* p) {
    uint32_t a;
    asm("{ .reg .u64 t; cvta.to.shared.u64 t, %1; cvt.u32.u64 %0, t; }"
        : "=r"(a) : "l"(p));
    return a;
}
#define CP16(d, s) asm volatile("cp.async.cg.shared.global [%0], [%1], 16;" :: "r"(d), "l"(s))
#define CPCOMMIT() asm volatile("cp.async.commit_group;")
#define CPWAIT2()  asm volatile("cp.async.wait_group 2;" ::: "memory")
#define CPWAIT0()  asm volatile("cp.async.wait_group 0;" ::: "memory")

// ---------------------------------------------------------------- prepW
__global__ void __launch_bounds__(256) prepW(
    const float* __restrict__ l0, const float* __restrict__ l1,
    const float* __restrict__ w1, const float* __restrict__ w2,
    float* __restrict__ W0T, float* __restrict__ W1T,
    float* __restrict__ U1T, float* __restrict__ U2T)
{
    int idx = blockIdx.x * 256 + threadIdx.x;
    if (idx < 256 * 288) {
        int n = idx / 288, k = idx % 288;
        W0T[idx] = (k < 283) ? tf32r(l0[k * 256 + n]) : 0.0f;
    }
    if (idx < 256 * 544) {
        int n = idx / 544, k = idx % 544;
        W1T[idx] = (k < 539) ? tf32r(l1[k * 256 + n]) : 0.0f;
    }
    if (idx < 64 * 40) {
        int n = idx / 40, k = idx % 40;
        U1T[idx] = tf32r(w1[k * 64 + n]);
    }
    if (idx < 256 * 64) {
        int n = idx / 64, k = idx % 64;
        U2T[idx] = tf32r(w2[k * 256 + n]);
    }
}

// ---------------------------------------------------------------- kernel A (gather only)
__global__ void __launch_bounds__(256) kernA(
    const float* __restrict__ coords,
    const float4* __restrict__ emb,
    float* __restrict__ feats)
{
    const int pid = blockIdx.x * 256 + threadIdx.x;

    float cx = coords[pid * 3 + 0];
    float cy = coords[pid * 3 + 1];
    float cz = coords[pid * 3 + 2];
    float nn = sqrtf(cx * cx + cy * cy + cz * cz);
    nn = fmaxf(nn, 1.1920929e-7f);
    if (nn > 1.0f) {
        float sc = 2.0f - 1.0f / nn;
        cx = sc * (cx / nn); cy = sc * (cy / nn); cz = sc * (cz / nn);
    }
    cx *= 0.5f; cy *= 0.5f; cz *= 0.5f;
    const float ux = (cx + 1.0f) * 0.5f;
    const float uy = (cy + 1.0f) * 0.5f;
    const float uz = (cz + 1.0f) * 0.5f;

    const int offs[10] = {0, 4096, 36864, 299008, 2396160,
                          4493312, 6590464, 8687616, 10784768, 12881920};
    float f[40];
#pragma unroll
    for (int i = 0; i < 40; i++) f[i] = 0.0f;

#pragma unroll
    for (int l = 0; l < 10; l++) {
        const int res = 16 << l;
        const float s = (float)res - 1.0f;
        float px = ux * s + 0.5f, py = uy * s + 0.5f, pz = uz * s + 0.5f;
        float gxf = floorf(px), gyf = floorf(py), gzf = floorf(pz);
        float fx = px - gxf, fy = py - gyf, fz = pz - gzf;
        int gx = (int)gxf, gy = (int)gyf, gz = (int)gzf;
#pragma unroll
        for (int c = 0; c < 8; c++) {
            const int b0 = c & 1, b1c = (c >> 1) & 1, b2c = (c >> 2) & 1;
            float w = (b0 ? fx : 1.0f - fx) * (b1c ? fy : 1.0f - fy)
                    * (b2c ? fz : 1.0f - fz);
            int idx;
            if (l < 4) {
                idx = (gx + b0) + (gy + b1c) * res + (gz + b2c) * res * res;
            } else {
                idx = (int)(((uint32_t)(gx + b0)
                           ^ ((uint32_t)(gy + b1c) * P1H)
                           ^ ((uint32_t)(gz + b2c) * P2H)) & HASH_MASK);
            }
            float4 e = __ldg(&emb[offs[l] + idx]);
            f[l * 4 + 0] += w * e.x; f[l * 4 + 1] += w * e.y;
            f[l * 4 + 2] += w * e.z; f[l * 4 + 3] += w * e.w;
        }
    }

    float4* out4 = (float4*)(feats + (size_t)pid * 40);
#pragma unroll
    for (int q = 0; q < 10; q++)
        out4[q] = make_float4(tf32r(f[q * 4]), tf32r(f[q * 4 + 1]),
                              tf32r(f[q * 4 + 2]), tf32r(f[q * 4 + 3]));
}

// ---------------------------------------------------------------- kernel M
// per 128-row tile: GEMM0a (40->64, relu) + GEMM0b (64->256), writes inp0+density
__global__ void __launch_bounds__(256, 1) kernM(
    const float* __restrict__ feats,
    const float* __restrict__ viewdirs,
    const float* __restrict__ U1T, const float* __restrict__ U2T,
    const float* __restrict__ b1g, const float* __restrict__ b2g,
    float* __restrict__ density, float* __restrict__ inp0)
{
    extern __shared__ float sm[];
    const uint32_t sb = smem_u32(sm);
    const int t = threadIdx.x;
    const int wid = t >> 5, lane = t & 31;
    const int g = lane >> 2, tq = lane & 3;
    const size_t base = (size_t)blockIdx.x * TILE_M;

    // zero pad columns (k = 40..51) of featsS and U1S
    for (int i = t; i < 128 * 12; i += 256) {
        int r = i / 12, c = 40 + i % 12;
        sm[M_FEATS + r * 52 + c] = 0.0f;
    }
    for (int i = t; i < 64 * 12; i += 256) {
        int r = i / 12, c = 40 + i % 12;
        sm[M_U1 + r * 52 + c] = 0.0f;
    }
    if (t < 64)  sm[M_B1 + t] = b1g[t];
    sm[M_B2 + t] = b2g[t];
    if (t < 64) {  // direnc for the tile's 2 rays (32 slots each, 27 real)
        int ray = (int)(base >> 6) + (t >> 5);
        int i = t & 31;
        float v = 0.0f;
        if (i < 27) {
            float dx = viewdirs[ray * 3 + 0];
            float dy = viewdirs[ray * 3 + 1];
            float dz = viewdirs[ray * 3 + 2];
            if (i < 3) v = (i == 0) ? dx : ((i == 1) ? dy : dz);
            else {
                int j = i - 3, deg = j / 6, rem = j % 6;
                float d = ((rem % 3) == 0) ? dx : (((rem % 3) == 1) ? dy : dz);
                float xb = d * (float)(1 << deg);
                v = (rem < 3) ? sinf(xb) : sinf(xb + 1.5707964f);
            }
        }
        sm[M_DE + (t >> 5) * 32 + i] = tf32r(v);
    }

    // async loads: feats tile, U1, U2
    for (int i = t; i < 128 * 10; i += 256) {
        int r = i / 10, seg = i % 10;
        CP16(sb + (M_FEATS + r * 52 + seg * 4) * 4,
             feats + (base + (size_t)r) * 40 + seg * 4);
    }
    for (int i = t; i < 64 * 10; i += 256) {
        int r = i / 10, seg = i % 10;
        CP16(sb + (M_U1 + r * 52 + seg * 4) * 4, U1T + (size_t)r * 40 + seg * 4);
    }
    for (int i = t; i < 256 * 16; i += 256) {
        int r = i / 16, seg = i % 16;
        CP16(sb + (M_U2 + r * 68 + seg * 4) * 4, U2T + (size_t)r * 64 + seg * 4);
    }
    CPCOMMIT();
    CPWAIT0();
    __syncthreads();

    // ---------------- GEMM0a: h = relu(feats @ U1 + b1), K=48, N=64 ----------
    {
        const int wm4 = wid & 3, wn2 = wid >> 2;
        const int m0 = wm4 * 32, n0 = wn2 * 32;
        float acc0[2][4][4];
#pragma unroll
        for (int mf = 0; mf < 2; mf++)
#pragma unroll
            for (int nf = 0; nf < 4; nf++) {
                int col = n0 + nf * 8 + tq * 2;
                acc0[mf][nf][0] = sm[M_B1 + col];
                acc0[mf][nf][1] = sm[M_B1 + col + 1];
                acc0[mf][nf][2] = sm[M_B1 + col];
                acc0[mf][nf][3] = sm[M_B1 + col + 1];
            }
#pragma unroll
        for (int ks = 0; ks < 6; ks++) {
            const int kk = ks * 8;
            uint32_t a[2][4], b[4][2];
#pragma unroll
            for (int mf = 0; mf < 2; mf++) {
                const int r0 = M_FEATS + (m0 + mf * 16 + g) * 52 + kk + tq;
                a[mf][0] = __float_as_uint(sm[r0]);
                a[mf][1] = __float_as_uint(sm[r0 + 8 * 52]);
                a[mf][2] = __float_as_uint(sm[r0 + 4]);
                a[mf][3] = __float_as_uint(sm[r0 + 8 * 52 + 4]);
            }
#pragma unroll
            for (int nf = 0; nf < 4; nf++) {
                const int rb = M_U1 + (n0 + nf * 8 + g) * 52 + kk + tq;
                b[nf][0] = __float_as_uint(sm[rb]);
                b[nf][1] = __float_as_uint(sm[rb + 4]);
            }
#pragma unroll
            for (int mf = 0; mf < 2; mf++)
#pragma unroll
                for (int nf = 0; nf < 4; nf++)
                    mma_tf32(acc0[mf][nf], a[mf][0], a[mf][1], a[mf][2], a[mf][3],
                             b[nf][0], b[nf][1]);
        }
        __syncthreads();  // featsS no longer needed... (hS region separate anyway)
#pragma unroll
        for (int mf = 0; mf < 2; mf++) {
            const int r0 = m0 + mf * 16 + g;
#pragma unroll
            for (int nf = 0; nf < 4; nf++) {
                const int col = n0 + nf * 8 + tq * 2;
                sm[M_H + r0 * 68 + col]       = tf32r(fmaxf(acc0[mf][nf][0], 0.0f));
                sm[M_H + r0 * 68 + col + 1]   = tf32r(fmaxf(acc0[mf][nf][1], 0.0f));
                sm[M_H + (r0+8) * 68 + col]   = tf32r(fmaxf(acc0[mf][nf][2], 0.0f));
                sm[M_H + (r0+8) * 68 + col+1] = tf32r(fmaxf(acc0[mf][nf][3], 0.0f));
            }
        }
    }
    __syncthreads();

    // ---------------- GEMM0b: bott = h @ U2 + b2, K=64, N=256 ----------------
    const int wm = wid & 1, wn = wid >> 1;
    const int m0 = wm * 64, n0w = wn * 64;
    float acc[4][8][4];
#pragma unroll
    for (int mf = 0; mf < 4; mf++)
#pragma unroll
        for (int nf = 0; nf < 8; nf++) {
            int col = n0w + nf * 8 + tq * 2;
            acc[mf][nf][0] = sm[M_B2 + col];
            acc[mf][nf][1] = sm[M_B2 + col + 1];
            acc[mf][nf][2] = sm[M_B2 + col];
            acc[mf][nf][3] = sm[M_B2 + col + 1];
        }
#pragma unroll
    for (int ks = 0; ks < 8; ks++) {
        const int kk = ks * 8;
        uint32_t a[4][4], b[8][2];
#pragma unroll
        for (int mf = 0; mf < 4; mf++) {
            const int r0 = M_H + (m0 + mf * 16 + g) * 68 + kk + tq;
            a[mf][0] = __float_as_uint(sm[r0]);
            a[mf][1] = __float_as_uint(sm[r0 + 8 * 68]);
            a[mf][2] = __float_as_uint(sm[r0 + 4]);
            a[mf][3] = __float_as_uint(sm[r0 + 8 * 68 + 4]);
        }
#pragma unroll
        for (int nf = 0; nf < 8; nf++) {
            const int rb = M_U2 + (n0w + nf * 8 + g) * 68 + kk + tq;
            b[nf][0] = __float_as_uint(sm[rb]);
            b[nf][1] = __float_as_uint(sm[rb + 4]);
        }
#pragma unroll
        for (int mf = 0; mf < 4; mf++)
#pragma unroll
            for (int nf = 0; nf < 8; nf++)
                mma_tf32(acc[mf][nf], a[mf][0], a[mf][1], a[mf][2], a[mf][3],
                         b[nf][0], b[nf][1]);
    }

    // epilogue: write bott (tf32) to inp0; density from col 0
#pragma unroll
    for (int mf = 0; mf < 4; mf++) {
        const int r0 = m0 + mf * 16 + g;
#pragma unroll
        for (int nf = 0; nf < 8; nf++) {
            const int col = n0w + nf * 8 + tq * 2;
            float2 v0 = make_float2(tf32r(acc[mf][nf][0]), tf32r(acc[mf][nf][1]));
            float2 v1 = make_float2(tf32r(acc[mf][nf][2]), tf32r(acc[mf][nf][3]));
            *(float2*)(inp0 + (base + (size_t)r0) * K1 + col)       = v0;
            *(float2*)(inp0 + (base + (size_t)(r0 + 8)) * K1 + col) = v1;
        }
        if (wn == 0 && tq == 0) {
            float r = acc[mf][0][0] - 1.0f;
            density[base + r0] = (r > 0.0f) ? (r + log1pf(expf(-r))) : log1pf(expf(r));
            r = acc[mf][0][2] - 1.0f;
            density[base + r0 + 8] = (r > 0.0f) ? (r + log1pf(expf(-r))) : log1pf(expf(r));
        }
    }
    // direnc columns 256..287
#pragma unroll
    for (int j = 0; j < 4; j++) {
        int i = t + 256 * j;
        int row = i >> 3, q = i & 7;
        float4 v = *(const float4*)&sm[M_DE + (row >> 6) * 32 + q * 4];
        *(float4*)(inp0 + (base + (size_t)row) * K1 + 256 + q * 4) = v;
    }
}

// ---------------------------------------------------------------- kernel B
// 256 threads, 8 warps: warp grid 2(M) x 4(N), warp tile 64x64, CTA tile 128x256
__device__ __forceinline__ void gemm_chunk(
    const float* __restrict__ As, int sa, int koff,
    const float* __restrict__ Ws,
    int m0, int n0w, int g, int t, float acc[4][8][4])
{
#pragma unroll
    for (int ks = 0; ks < 2; ks++) {
        const int kk = koff + ks * 8;
        uint32_t a[4][4], b[8][2];
#pragma unroll
        for (int mf = 0; mf < 4; mf++) {
            const int r0 = (m0 + mf * 16 + g) * sa + kk + t;
            a[mf][0] = __float_as_uint(As[r0]);
            a[mf][1] = __float_as_uint(As[r0 + 8 * sa]);
            a[mf][2] = __float_as_uint(As[r0 + 4]);
            a[mf][3] = __float_as_uint(As[r0 + 8 * sa + 4]);
        }
#pragma unroll
        for (int nf = 0; nf < 8; nf++) {
            const int rb = (n0w + nf * 8 + g) * 20 + ks * 8 + t;
            b[nf][0] = __float_as_uint(Ws[rb]);
            b[nf][1] = __float_as_uint(Ws[rb + 4]);
        }
#pragma unroll
        for (int mf = 0; mf < 4; mf++)
#pragma unroll
            for (int nf = 0; nf < 8; nf++)
                mma_tf32(acc[mf][nf], a[mf][0], a[mf][1], a[mf][2], a[mf][3],
                         b[nf][0], b[nf][1]);
    }
}

__global__ void __launch_bounds__(256, 1) kernB(
    const float* __restrict__ inp0,
    const float* __restrict__ W0T, const float* __restrict__ W1T,
    const float* __restrict__ b0g, const float* __restrict__ b1g,
    const float* __restrict__ rgbwg, const float* __restrict__ rgbbg,
    float* __restrict__ out_rgb)
{
    extern __shared__ char smem[];
    float* Xs = (float*)smem;                         // [128][260]
    float* s_b0 = (float*)(smem + BIAS_OFF);          // [256]
    float* s_b1 = (float*)(smem + BIAS_OFF + 1024);   // [256]
    float* s_rw = (float*)(smem + BIAS_OFF + 2048);   // [256][3]
    float* s_rb = (float*)(smem + BIAS_OFF + 5120);   // [3]
    const uint32_t sb = smem_u32(smem);

    const int t = threadIdx.x;
    const int wid = t >> 5, lane = t & 31;
    const int g = lane >> 2, tq = lane & 3;
    const int wm = wid & 1, wn = wid >> 1;
    const int m0 = wm * 64, n0w = wn * 64;
    const size_t base = (size_t)blockIdx.x * TILE_M;

    s_b0[t] = b0g[t];
    s_b1[t] = b1g[t];
    for (int i = t; i < 768; i += 256) s_rw[i] = rgbwg[i];
    if (t < 3) s_rb[t] = rgbbg[t];
    __syncthreads();

    auto issue_load = [&](int p) {
        const uint32_t abase = sb + A_SM_OFF + (uint32_t)(p % 3) * ABUF_B;
        const uint32_t wbase = sb + W_SM_OFF + (uint32_t)(p % 3) * WBUF_B;
        const float* wsrc; int wld, wcol, acol; bool hasA;
        if (p < 18)      { wsrc = W0T; wld = 288; wcol = p * 16; hasA = true;  acol = p * 16; }
        else if (p < 34) { wsrc = W1T; wld = 544; wcol = (p - 18) * 16; hasA = false; acol = 0; }
        else             { wsrc = W1T; wld = 544; wcol = 256 + (p - 34) * 16; hasA = true; acol = (p - 34) * 16; }
#pragma unroll
        for (int j = 0; j < 4; j++) {
            int i = t + 256 * j, row = i >> 2, seg = i & 3;
            CP16(wbase + (uint32_t)row * 80u + (uint32_t)seg * 16u,
                 wsrc + (size_t)row * wld + wcol + seg * 4);
        }
        if (hasA) {
#pragma unroll
            for (int j = 0; j < 2; j++) {
                int i = t + 256 * j, row = i >> 2, seg = i & 3;
                CP16(abase + (uint32_t)row * 80u + (uint32_t)seg * 16u,
                     inp0 + (base + (size_t)row) * K1 + acol + seg * 4);
            }
        }
    };

    float acc[4][8][4];
#pragma unroll
    for (int mf = 0; mf < 4; mf++)
#pragma unroll
        for (int nf = 0; nf < 8; nf++) {
            int col = n0w + nf * 8 + tq * 2;
            acc[mf][nf][0] = s_b0[col];
            acc[mf][nf][1] = s_b0[col + 1];
            acc[mf][nf][2] = s_b0[col];
            acc[mf][nf][3] = s_b0[col + 1];
        }

    issue_load(0); CPCOMMIT();
    issue_load(1); CPCOMMIT();
    issue_load(2); CPCOMMIT();

    for (int c = 0; c < NCHUNK; c++) {
        CPWAIT2();
        __syncthreads();

        const float* Ws = (const float*)(smem + W_SM_OFF + (c % 3) * WBUF_B);
        if (c >= 18 && c < 34) {
            gemm_chunk(Xs, XSTR, (c - 18) * 16, Ws, m0, n0w, g, tq, acc);
        } else {
            const float* As = (const float*)(smem + A_SM_OFF + (c % 3) * ABUF_B);
            gemm_chunk(As, 20, 0, Ws, m0, n0w, g, tq, acc);
        }

        if (c == 17) {
#pragma unroll
            for (int mf = 0; mf < 4; mf++) {
                const int r0 = m0 + mf * 16 + g;
#pragma unroll
                for (int nf = 0; nf < 8; nf++) {
                    const int col = n0w + nf * 8 + tq * 2;
                    Xs[r0 * XSTR + col]       = tf32r(fmaxf(acc[mf][nf][0], 0.0f));
                    Xs[r0 * XSTR + col + 1]   = tf32r(fmaxf(acc[mf][nf][1], 0.0f));
                    Xs[(r0+8) * XSTR + col]   = tf32r(fmaxf(acc[mf][nf][2], 0.0f));
                    Xs[(r0+8) * XSTR + col+1] = tf32r(fmaxf(acc[mf][nf][3], 0.0f));
                    acc[mf][nf][0] = s_b1[col];
                    acc[mf][nf][1] = s_b1[col + 1];
                    acc[mf][nf][2] = s_b1[col];
                    acc[mf][nf][3] = s_b1[col + 1];
                }
            }
        }
        __syncthreads();
        if (c + 3 < NCHUNK) issue_load(c + 3);
        CPCOMMIT();
    }

    // ---------------- rgb head ----------------
    float p[8][3];
#pragma unroll
    for (int r = 0; r < 8; r++) { p[r][0] = 0; p[r][1] = 0; p[r][2] = 0; }
#pragma unroll
    for (int mf = 0; mf < 4; mf++)
#pragma unroll
        for (int nf = 0; nf < 8; nf++) {
            const int col0 = n0w + nf * 8 + tq * 2, col1 = col0 + 1;
            float y00 = fmaxf(acc[mf][nf][0], 0.0f);
            float y01 = fmaxf(acc[mf][nf][1], 0.0f);
            float y10 = fmaxf(acc[mf][nf][2], 0.0f);
            float y11 = fmaxf(acc[mf][nf][3], 0.0f);
#pragma unroll
            for (int ch = 0; ch < 3; ch++) {
                float w0 = s_rw[col0 * 3 + ch], w1 = s_rw[col1 * 3 + ch];
                p[mf * 2 + 0][ch] += y00 * w0 + y01 * w1;
                p[mf * 2 + 1][ch] += y10 * w0 + y11 * w1;
            }
        }
#pragma unroll
    for (int r = 0; r < 8; r++)
#pragma unroll
        for (int ch = 0; ch < 3; ch++) {
            p[r][ch] += __shfl_xor_sync(0xffffffffu, p[r][ch], 1);
            p[r][ch] += __shfl_xor_sync(0xffffffffu, p[r][ch], 2);
        }

    float* part = (float*)(smem + A_SM_OFF);  // [4 wn][128 rows][3]
    __syncthreads();
    if (tq == 0) {
#pragma unroll
        for (int mf = 0; mf < 4; mf++)
#pragma unroll
            for (int h = 0; h < 2; h++) {
                int row = m0 + mf * 16 + g + 8 * h;
                int r = mf * 2 + h;
                part[(wn * 128 + row) * 3 + 0] = p[r][0];
                part[(wn * 128 + row) * 3 + 1] = p[r][1];
                part[(wn * 128 + row) * 3 + 2] = p[r][2];
            }
    }
    __syncthreads();
    if (t < 128) {
        const size_t gidx = base + t;
#pragma unroll
        for (int ch = 0; ch < 3; ch++) {
            float v = part[(0 * 128 + t) * 3 + ch] + part[(1 * 128 + t) * 3 + ch]
                    + part[(2 * 128 + t) * 3 + ch] + part[(3 * 128 + t) * 3 + ch]
                    + s_rb[ch];
            float sg = 1.0f / (1.0f + expf(-v));
            out_rgb[gidx * 3 + ch] = sg * 1.002f - 0.001f;
        }
    }
}

// ---------------------------------------------------------------- launch
extern "C" void kernel_launch(void* const* d_in, const int* in_sizes, int n_in,
                              void* d_out, int out_size)
{
    const float*  coords   = (const float*)d_in[0];
    const float*  viewdirs = (const float*)d_in[2];
    const float4* emb      = (const float4*)d_in[3];
    const float*  w1       = (const float*)d_in[4];
    const float*  b1       = (const float*)d_in[5];
    const float*  w2       = (const float*)d_in[6];
    const float*  b2       = (const float*)d_in[7];
    const float*  lin0_w   = (const float*)d_in[8];
    const float*  lin0_b   = (const float*)d_in[9];
    const float*  lin1_w   = (const float*)d_in[10];
    const float*  lin1_b   = (const float*)d_in[11];
    const float*  rgb_w    = (const float*)d_in[12];
    const float*  rgb_b    = (const float*)d_in[13];

    float* dout    = (float*)d_out;
    float* density = dout;
    float* rgb     = dout + NPTS;

    float *feats, *inp0, *W0T, *W1T, *U1T, *U2T;
    cudaGetSymbolAddress((void**)&feats, g_feats);
    cudaGetSymbolAddress((void**)&inp0, g_inp0);
    cudaGetSymbolAddress((void**)&W0T, g_W0T);
    cudaGetSymbolAddress((void**)&W1T, g_W1T);
    cudaGetSymbolAddress((void**)&U1T, g_U1T);
    cudaGetSymbolAddress((void**)&U2T, g_U2T);

    cudaFuncSetAttribute(kernM, cudaFuncAttributeMaxDynamicSharedMemorySize, SMEMM_BYTES);
    cudaFuncSetAttribute(kernB, cudaFuncAttributeMaxDynamicSharedMemorySize, SMEMB_BYTES);

    prepW<<<544, 256>>>(lin0_w, lin1_w, w1, w2, W0T, W1T, U1T, U2T);
    kernA<<<NPTS / 256, 256>>>(coords, emb, feats);
    kernM<<<NTILES, 256, SMEMM_BYTES>>>(feats, viewdirs, U1T, U2T, b1, b2,
                                        density, inp0);
    kernB<<<NTILES, 256, SMEMB_BYTES>>>(inp0, W0T, W1T, lin0_b, lin1_b,
                                        rgb_w, rgb_b, rgb);
}

// round 5
// speedup vs baseline: 4.9442x; 1.2473x over previous
#include <cuda_runtime.h>
#include <cuda_bf16.h>
#include <math.h>
#include <stdint.h>

// ---------------------------------------------------------------- constants
#define NPTS (4096 * 64)
#define NRAYS 4096
#define HASH_MASK 2097151u
#define P1H 2654435761u
#define P2H 805459861u

#define TILE_M 128
#define NTILES (NPTS / TILE_M)   // 2048
#define K1 288                    // 283 padded

// kernB chunk schedule: 18 (gemm1) + 16 (gemm2 x-part) + 18 (gemm2 inp-part)
#define NCHUNK 52

// kernB smem layout (bytes), bf16 activations/weights
#define XSE 264                              // X panel element stride
#define X_BYTES (128 * XSE * 2)              // 67584
#define A_SM_OFF X_BYTES
#define ABUF_B (128 * 24 * 2)                // 6144  (row stride 24 bf16)
#define W_SM_OFF (A_SM_OFF + 3 * ABUF_B)     // 86016
#define WBUF_B (256 * 24 * 2)                // 12288
#define BIAS_OFF (W_SM_OFF + 3 * WBUF_B)     // 122880
#define SMEMB_BYTES (BIAS_OFF + 5136)        // 128016

// kernM smem layout (floats)
#define M_FEATS 0                 // [128][52]
#define M_H     (128 * 52)        // [128][68]
#define M_U1    (M_H + 128 * 68)  // [64][52]
#define M_U2    (M_U1 + 64 * 52)  // [256][68]
#define M_B1    (M_U2 + 256 * 68)
#define M_B2    (M_B1 + 64)
#define M_DE    (M_B2 + 256)      // [2][32]
#define SMEMM_FLOATS (M_DE + 64)
#define SMEMM_BYTES (SMEMM_FLOATS * 4)

// ---------------------------------------------------------------- globals
__device__ float g_feats[(size_t)NPTS * 40];
__device__ __nv_bfloat16 g_inp0[(size_t)NPTS * K1];  // [N,288] bf16
__device__ __nv_bfloat16 g_W0T[256 * 288];           // lin0_w^T bf16, padded
__device__ __nv_bfloat16 g_W1T[256 * 544];           // lin1_w^T bf16, padded
__device__ float g_U1T[64 * 40];                     // w1^T (tf32)
__device__ float g_U2T[256 * 64];                    // w2^T (tf32)

// ---------------------------------------------------------------- helpers
__device__ __forceinline__ float tf32r(float v) {
    uint32_t u;
    asm("cvt.rna.tf32.f32 %0, %1;" : "=r"(u) : "f"(v));
    return __uint_as_float(u);
}
__device__ __forceinline__ uint32_t bf16pack(float lo, float hi) {
    uint32_t d;
    asm("cvt.rn.bf16x2.f32 %0, %1, %2;" : "=r"(d) : "f"(hi), "f"(lo));
    return d;
}
__device__ __forceinline__ void mma_tf32(float c[4],
    uint32_t a0, uint32_t a1, uint32_t a2, uint32_t a3,
    uint32_t b0, uint32_t b1)
{
    asm volatile(
        "mma.sync.aligned.m16n8k8.row.col.f32.tf32.tf32.f32 "
        "{%0,%1,%2,%3},{%4,%5,%6,%7},{%8,%9},{%0,%1,%2,%3};"
        : "+f"(c[0]), "+f"(c[1]), "+f"(c[2]), "+f"(c[3])
        : "r"(a0), "r"(a1), "r"(a2), "r"(a3), "r"(b0), "r"(b1));
}
__device__ __forceinline__ void mma_bf16(float c[4],
    uint32_t a0, uint32_t a1, uint32_t a2, uint32_t a3,
    uint32_t b0, uint32_t b1)
{
    asm volatile(
        "mma.sync.aligned.m16n8k16.row.col.f32.bf16.bf16.f32 "
        "{%0,%1,%2,%3},{%4,%5,%6,%7},{%8,%9},{%0,%1,%2,%3};"
        : "+f"(c[0]), "+f"(c[1]), "+f"(c[2]), "+f"(c[3])
        : "r"(a0), "r"(a1), "r"(a2), "r"(a3), "r"(b0), "r"(b1));
}
__device__ __forceinline__ uint32_t smem_u32(const void* p) {
    uint32_t a;
    asm("{ .reg .u64 t; cvta.to.shared.u64 t, %1; cvt.u32.u64 %0, t; }"
        : "=r"(a) : "l"(p));
    return a;
}
#define CP16(d, s) asm volatile("cp.async.cg.shared.global [%0], [%1], 16;" :: "r"(d), "l"(s))
#define CPCOMMIT() asm volatile("cp.async.commit_group;")
#define CPWAIT2()  asm volatile("cp.async.wait_group 2;" ::: "memory")
#define CPWAIT0()  asm volatile("cp.async.wait_group 0;" ::: "memory")

// ---------------------------------------------------------------- prepW
__global__ void __launch_bounds__(256) prepW(
    const float* __restrict__ l0, const float* __restrict__ l1,
    const float* __restrict__ w1, const float* __restrict__ w2,
    __nv_bfloat16* __restrict__ W0T, __nv_bfloat16* __restrict__ W1T,
    float* __restrict__ U1T, float* __restrict__ U2T)
{
    int idx = blockIdx.x * 256 + threadIdx.x;
    if (idx < 256 * 288) {
        int n = idx / 288, k = idx % 288;
        W0T[idx] = __float2bfloat16((k < 283) ? l0[k * 256 + n] : 0.0f);
    }
    if (idx < 256 * 544) {
        int n = idx / 544, k = idx % 544;
        W1T[idx] = __float2bfloat16((k < 539) ? l1[k * 256 + n] : 0.0f);
    }
    if (idx < 64 * 40) {
        int n = idx / 40, k = idx % 40;
        U1T[idx] = tf32r(w1[k * 64 + n]);
    }
    if (idx < 256 * 64) {
        int n = idx / 64, k = idx % 64;
        U2T[idx] = tf32r(w2[k * 256 + n]);
    }
}

// ---------------------------------------------------------------- kernel A (gather only)
__global__ void __launch_bounds__(256) kernA(
    const float* __restrict__ coords,
    const float4* __restrict__ emb,
    float* __restrict__ feats)
{
    const int pid = blockIdx.x * 256 + threadIdx.x;

    float cx = coords[pid * 3 + 0];
    float cy = coords[pid * 3 + 1];
    float cz = coords[pid * 3 + 2];
    float nn = sqrtf(cx * cx + cy * cy + cz * cz);
    nn = fmaxf(nn, 1.1920929e-7f);
    if (nn > 1.0f) {
        float sc = 2.0f - 1.0f / nn;
        cx = sc * (cx / nn); cy = sc * (cy / nn); cz = sc * (cz / nn);
    }
    cx *= 0.5f; cy *= 0.5f; cz *= 0.5f;
    const float ux = (cx + 1.0f) * 0.5f;
    const float uy = (cy + 1.0f) * 0.5f;
    const float uz = (cz + 1.0f) * 0.5f;

    const int offs[10] = {0, 4096, 36864, 299008, 2396160,
                          4493312, 6590464, 8687616, 10784768, 12881920};
    float f[40];
#pragma unroll
    for (int i = 0; i < 40; i++) f[i] = 0.0f;

#pragma unroll
    for (int l = 0; l < 10; l++) {
        const int res = 16 << l;
        const float s = (float)res - 1.0f;
        float px = ux * s + 0.5f, py = uy * s + 0.5f, pz = uz * s + 0.5f;
        float gxf = floorf(px), gyf = floorf(py), gzf = floorf(pz);
        float fx = px - gxf, fy = py - gyf, fz = pz - gzf;
        int gx = (int)gxf, gy = (int)gyf, gz = (int)gzf;
#pragma unroll
        for (int c = 0; c < 8; c++) {
            const int b0 = c & 1, b1c = (c >> 1) & 1, b2c = (c >> 2) & 1;
            float w = (b0 ? fx : 1.0f - fx) * (b1c ? fy : 1.0f - fy)
                    * (b2c ? fz : 1.0f - fz);
            int idx;
            if (l < 4) {
                idx = (gx + b0) + (gy + b1c) * res + (gz + b2c) * res * res;
            } else {
                idx = (int)(((uint32_t)(gx + b0)
                           ^ ((uint32_t)(gy + b1c) * P1H)
                           ^ ((uint32_t)(gz + b2c) * P2H)) & HASH_MASK);
            }
            float4 e = __ldg(&emb[offs[l] + idx]);
            f[l * 4 + 0] += w * e.x; f[l * 4 + 1] += w * e.y;
            f[l * 4 + 2] += w * e.z; f[l * 4 + 3] += w * e.w;
        }
    }

    float4* out4 = (float4*)(feats + (size_t)pid * 40);
#pragma unroll
    for (int q = 0; q < 10; q++)
        out4[q] = make_float4(tf32r(f[q * 4]), tf32r(f[q * 4 + 1]),
                              tf32r(f[q * 4 + 2]), tf32r(f[q * 4 + 3]));
}

// ---------------------------------------------------------------- kernel M
// per 128-row tile: GEMM0a (40->64, relu) + GEMM0b (64->256), writes inp0+density
__global__ void __launch_bounds__(256, 1) kernM(
    const float* __restrict__ feats,
    const float* __restrict__ viewdirs,
    const float* __restrict__ U1T, const float* __restrict__ U2T,
    const float* __restrict__ b1g, const float* __restrict__ b2g,
    float* __restrict__ density, __nv_bfloat16* __restrict__ inp0)
{
    extern __shared__ float sm[];
    const uint32_t sb = smem_u32(sm);
    const int t = threadIdx.x;
    const int wid = t >> 5, lane = t & 31;
    const int g = lane >> 2, tq = lane & 3;
    const size_t base = (size_t)blockIdx.x * TILE_M;

    for (int i = t; i < 128 * 12; i += 256) {
        int r = i / 12, c = 40 + i % 12;
        sm[M_FEATS + r * 52 + c] = 0.0f;
    }
    for (int i = t; i < 64 * 12; i += 256) {
        int r = i / 12, c = 40 + i % 12;
        sm[M_U1 + r * 52 + c] = 0.0f;
    }
    if (t < 64)  sm[M_B1 + t] = b1g[t];
    sm[M_B2 + t] = b2g[t];
    if (t < 64) {
        int ray = (int)(base >> 6) + (t >> 5);
        int i = t & 31;
        float v = 0.0f;
        if (i < 27) {
            float dx = viewdirs[ray * 3 + 0];
            float dy = viewdirs[ray * 3 + 1];
            float dz = viewdirs[ray * 3 + 2];
            if (i < 3) v = (i == 0) ? dx : ((i == 1) ? dy : dz);
            else {
                int j = i - 3, deg = j / 6, rem = j % 6;
                float d = ((rem % 3) == 0) ? dx : (((rem % 3) == 1) ? dy : dz);
                float xb = d * (float)(1 << deg);
                v = (rem < 3) ? sinf(xb) : sinf(xb + 1.5707964f);
            }
        }
        sm[M_DE + (t >> 5) * 32 + i] = v;
    }

    for (int i = t; i < 128 * 10; i += 256) {
        int r = i / 10, seg = i % 10;
        CP16(sb + (M_FEATS + r * 52 + seg * 4) * 4,
             feats + (base + (size_t)r) * 40 + seg * 4);
    }
    for (int i = t; i < 64 * 10; i += 256) {
        int r = i / 10, seg = i % 10;
        CP16(sb + (M_U1 + r * 52 + seg * 4) * 4, U1T + (size_t)r * 40 + seg * 4);
    }
    for (int i = t; i < 256 * 16; i += 256) {
        int r = i / 16, seg = i % 16;
        CP16(sb + (M_U2 + r * 68 + seg * 4) * 4, U2T + (size_t)r * 64 + seg * 4);
    }
    CPCOMMIT();
    CPWAIT0();
    __syncthreads();

    // GEMM0a: h = relu(feats @ U1 + b1), K=48, N=64
    {
        const int wm4 = wid & 3, wn2 = wid >> 2;
        const int m0 = wm4 * 32, n0 = wn2 * 32;
        float acc0[2][4][4];
#pragma unroll
        for (int mf = 0; mf < 2; mf++)
#pragma unroll
            for (int nf = 0; nf < 4; nf++) {
                int col = n0 + nf * 8 + tq * 2;
                acc0[mf][nf][0] = sm[M_B1 + col];
                acc0[mf][nf][1] = sm[M_B1 + col + 1];
                acc0[mf][nf][2] = sm[M_B1 + col];
                acc0[mf][nf][3] = sm[M_B1 + col + 1];
            }
#pragma unroll
        for (int ks = 0; ks < 6; ks++) {
            const int kk = ks * 8;
            uint32_t a[2][4], b[4][2];
#pragma unroll
            for (int mf = 0; mf < 2; mf++) {
                const int r0 = M_FEATS + (m0 + mf * 16 + g) * 52 + kk + tq;
                a[mf][0] = __float_as_uint(sm[r0]);
                a[mf][1] = __float_as_uint(sm[r0 + 8 * 52]);
                a[mf][2] = __float_as_uint(sm[r0 + 4]);
                a[mf][3] = __float_as_uint(sm[r0 + 8 * 52 + 4]);
            }
#pragma unroll
            for (int nf = 0; nf < 4; nf++) {
                const int rb = M_U1 + (n0 + nf * 8 + g) * 52 + kk + tq;
                b[nf][0] = __float_as_uint(sm[rb]);
                b[nf][1] = __float_as_uint(sm[rb + 4]);
            }
#pragma unroll
            for (int mf = 0; mf < 2; mf++)
#pragma unroll
                for (int nf = 0; nf < 4; nf++)
                    mma_tf32(acc0[mf][nf], a[mf][0], a[mf][1], a[mf][2], a[mf][3],
                             b[nf][0], b[nf][1]);
        }
        __syncthreads();
#pragma unroll
        for (int mf = 0; mf < 2; mf++) {
            const int r0 = m0 + mf * 16 + g;
#pragma unroll
            for (int nf = 0; nf < 4; nf++) {
                const int col = n0 + nf * 8 + tq * 2;
                sm[M_H + r0 * 68 + col]       = tf32r(fmaxf(acc0[mf][nf][0], 0.0f));
                sm[M_H + r0 * 68 + col + 1]   = tf32r(fmaxf(acc0[mf][nf][1], 0.0f));
                sm[M_H + (r0+8) * 68 + col]   = tf32r(fmaxf(acc0[mf][nf][2], 0.0f));
                sm[M_H + (r0+8) * 68 + col+1] = tf32r(fmaxf(acc0[mf][nf][3], 0.0f));
            }
        }
    }
    __syncthreads();

    // GEMM0b: bott = h @ U2 + b2, K=64, N=256
    const int wm = wid & 1, wn = wid >> 1;
    const int m0 = wm * 64, n0w = wn * 64;
    float acc[4][8][4];
#pragma unroll
    for (int mf = 0; mf < 4; mf++)
#pragma unroll
        for (int nf = 0; nf < 8; nf++) {
            int col = n0w + nf * 8 + tq * 2;
            acc[mf][nf][0] = sm[M_B2 + col];
            acc[mf][nf][1] = sm[M_B2 + col + 1];
            acc[mf][nf][2] = sm[M_B2 + col];
            acc[mf][nf][3] = sm[M_B2 + col + 1];
        }
#pragma unroll
    for (int ks = 0; ks < 8; ks++) {
        const int kk = ks * 8;
        uint32_t a[4][4], b[8][2];
#pragma unroll
        for (int mf = 0; mf < 4; mf++) {
            const int r0 = M_H + (m0 + mf * 16 + g) * 68 + kk + tq;
            a[mf][0] = __float_as_uint(sm[r0]);
            a[mf][1] = __float_as_uint(sm[r0 + 8 * 68]);
            a[mf][2] = __float_as_uint(sm[r0 + 4]);
            a[mf][3] = __float_as_uint(sm[r0 + 8 * 68 + 4]);
        }
#pragma unroll
        for (int nf = 0; nf < 8; nf++) {
            const int rb = M_U2 + (n0w + nf * 8 + g) * 68 + kk + tq;
            b[nf][0] = __float_as_uint(sm[rb]);
            b[nf][1] = __float_as_uint(sm[rb + 4]);
        }
#pragma unroll
        for (int mf = 0; mf < 4; mf++)
#pragma unroll
            for (int nf = 0; nf < 8; nf++)
                mma_tf32(acc[mf][nf], a[mf][0], a[mf][1], a[mf][2], a[mf][3],
                         b[nf][0], b[nf][1]);
    }

    // epilogue: write bott (bf16 pairs) to inp0; density from col 0
#pragma unroll
    for (int mf = 0; mf < 4; mf++) {
        const int r0 = m0 + mf * 16 + g;
#pragma unroll
        for (int nf = 0; nf < 8; nf++) {
            const int col = n0w + nf * 8 + tq * 2;
            uint32_t v0 = bf16pack(acc[mf][nf][0], acc[mf][nf][1]);
            uint32_t v1 = bf16pack(acc[mf][nf][2], acc[mf][nf][3]);
            *(uint32_t*)(inp0 + (base + (size_t)r0) * K1 + col)       = v0;
            *(uint32_t*)(inp0 + (base + (size_t)(r0 + 8)) * K1 + col) = v1;
        }
        if (wn == 0 && tq == 0) {
            float r = acc[mf][0][0] - 1.0f;
            density[base + r0] = (r > 0.0f) ? (r + log1pf(expf(-r))) : log1pf(expf(r));
            r = acc[mf][0][2] - 1.0f;
            density[base + r0 + 8] = (r > 0.0f) ? (r + log1pf(expf(-r))) : log1pf(expf(r));
        }
    }
    // direnc columns 256..287 (16 bf16 pairs per row)
#pragma unroll
    for (int j = 0; j < 8; j++) {
        int i = t + 256 * j;
        int row = i >> 4, q = i & 15;
        const float* de = &sm[M_DE + (row >> 6) * 32];
        uint32_t v = bf16pack(de[q * 2], de[q * 2 + 1]);
        *(uint32_t*)(inp0 + (base + (size_t)row) * K1 + 256 + q * 2) = v;
    }
}

// ---------------------------------------------------------------- kernel B (bf16 mma)
// 512 threads, 16 warps: warp grid 2(M) x 8(N), warp tile 64x32, CTA tile 128x256
__device__ __forceinline__ void gemm_chunk_bf16(
    const __nv_bfloat16* __restrict__ As, int saE, int koffE,
    const __nv_bfloat16* __restrict__ Ws,
    int m0, int n0, int g, int tq, float acc[4][4][4])
{
    uint32_t a[4][4], b[4][2];
#pragma unroll
    for (int mf = 0; mf < 4; mf++) {
        const __nv_bfloat16* ap = As + (m0 + mf * 16 + g) * saE + koffE + tq * 2;
        a[mf][0] = *(const uint32_t*)ap;
        a[mf][1] = *(const uint32_t*)(ap + 8 * saE);
        a[mf][2] = *(const uint32_t*)(ap + 8);
        a[mf][3] = *(const uint32_t*)(ap + 8 * saE + 8);
    }
#pragma unroll
    for (int nf = 0; nf < 4; nf++) {
        const __nv_bfloat16* bp = Ws + (n0 + nf * 8 + g) * 24 + tq * 2;
        b[nf][0] = *(const uint32_t*)bp;
        b[nf][1] = *(const uint32_t*)(bp + 8);
    }
#pragma unroll
    for (int mf = 0; mf < 4; mf++)
#pragma unroll
        for (int nf = 0; nf < 4; nf++)
            mma_bf16(acc[mf][nf], a[mf][0], a[mf][1], a[mf][2], a[mf][3],
                     b[nf][0], b[nf][1]);
}

__global__ void __launch_bounds__(512, 1) kernB(
    const __nv_bfloat16* __restrict__ inp0,
    const __nv_bfloat16* __restrict__ W0T, const __nv_bfloat16* __restrict__ W1T,
    const float* __restrict__ b0g, const float* __restrict__ b1g,
    const float* __restrict__ rgbwg, const float* __restrict__ rgbbg,
    float* __restrict__ out_rgb)
{
    extern __shared__ char smem[];
    __nv_bfloat16* Xs = (__nv_bfloat16*)smem;         // [128][264] bf16
    float* s_b0 = (float*)(smem + BIAS_OFF);          // [256]
    float* s_b1 = (float*)(smem + BIAS_OFF + 1024);   // [256]
    float* s_rw = (float*)(smem + BIAS_OFF + 2048);   // [256][3]
    float* s_rb = (float*)(smem + BIAS_OFF + 5120);   // [3]
    const uint32_t sb = smem_u32(smem);

    const int t = threadIdx.x;
    const int wid = t >> 5, lane = t & 31;
    const int g = lane >> 2, tq = lane & 3;
    const int wm = wid & 1, wn = wid >> 1;
    const int m0 = wm * 64, n0 = wn * 32;
    const size_t base = (size_t)blockIdx.x * TILE_M;

    if (t < 256) { s_b0[t] = b0g[t]; s_b1[t] = b1g[t]; }
    for (int i = t; i < 768; i += 512) s_rw[i] = rgbwg[i];
    if (t < 3) s_rb[t] = rgbbg[t];
    __syncthreads();

    auto issue_load = [&](int p) {
        const uint32_t abase = sb + A_SM_OFF + (uint32_t)(p % 3) * ABUF_B;
        const uint32_t wbase = sb + W_SM_OFF + (uint32_t)(p % 3) * WBUF_B;
        const __nv_bfloat16* wsrc; int wld, wcol, acol; bool hasA;
        if (p < 18)      { wsrc = W0T; wld = 288; wcol = p * 16; hasA = true;  acol = p * 16; }
        else if (p < 34) { wsrc = W1T; wld = 544; wcol = (p - 18) * 16; hasA = false; acol = 0; }
        else             { wsrc = W1T; wld = 544; wcol = 256 + (p - 34) * 16; hasA = true; acol = (p - 34) * 16; }
        {   // 256 rows x 2 segs of 16B
            int row = t >> 1, seg = t & 1;
            CP16(wbase + (uint32_t)row * 48u + (uint32_t)seg * 16u,
                 wsrc + (size_t)row * wld + wcol + seg * 8);
        }
        if (hasA && t < 256) {  // 128 rows x 2 segs
            int row = t >> 1, seg = t & 1;
            CP16(abase + (uint32_t)row * 48u + (uint32_t)seg * 16u,
                 inp0 + (base + (size_t)row) * K1 + acol + seg * 8);
        }
    };

    float acc[4][4][4];
#pragma unroll
    for (int mf = 0; mf < 4; mf++)
#pragma unroll
        for (int nf = 0; nf < 4; nf++) {
            int col = n0 + nf * 8 + tq * 2;
            acc[mf][nf][0] = s_b0[col];
            acc[mf][nf][1] = s_b0[col + 1];
            acc[mf][nf][2] = s_b0[col];
            acc[mf][nf][3] = s_b0[col + 1];
        }

    issue_load(0); CPCOMMIT();
    issue_load(1); CPCOMMIT();
    issue_load(2); CPCOMMIT();

    for (int c = 0; c < NCHUNK; c++) {
        CPWAIT2();
        __syncthreads();

        const __nv_bfloat16* Ws =
            (const __nv_bfloat16*)(smem + W_SM_OFF + (c % 3) * WBUF_B);
        if (c >= 18 && c < 34) {
            gemm_chunk_bf16(Xs, XSE, (c - 18) * 16, Ws, m0, n0, g, tq, acc);
        } else {
            const __nv_bfloat16* As =
                (const __nv_bfloat16*)(smem + A_SM_OFF + (c % 3) * ABUF_B);
            gemm_chunk_bf16(As, 24, 0, Ws, m0, n0, g, tq, acc);
        }

        if (c == 17) {
            // epilogue 1: relu(x + b0) -> bf16 -> X panel; reset acc to b1
#pragma unroll
            for (int mf = 0; mf < 4; mf++) {
                const int r0 = m0 + mf * 16 + g;
#pragma unroll
                for (int nf = 0; nf < 4; nf++) {
                    const int col = n0 + nf * 8 + tq * 2;
                    uint32_t v0 = bf16pack(fmaxf(acc[mf][nf][0], 0.0f),
                                           fmaxf(acc[mf][nf][1], 0.0f));
                    uint32_t v1 = bf16pack(fmaxf(acc[mf][nf][2], 0.0f),
                                           fmaxf(acc[mf][nf][3], 0.0f));
                    *(uint32_t*)(Xs + r0 * XSE + col)       = v0;
                    *(uint32_t*)(Xs + (r0 + 8) * XSE + col) = v1;
                    acc[mf][nf][0] = s_b1[col];
                    acc[mf][nf][1] = s_b1[col + 1];
                    acc[mf][nf][2] = s_b1[col];
                    acc[mf][nf][3] = s_b1[col + 1];
                }
            }
        }
        __syncthreads();
        if (c + 3 < NCHUNK) issue_load(c + 3);
        CPCOMMIT();
    }

    // ---------------- rgb head ----------------
    float p[8][3];
#pragma unroll
    for (int r = 0; r < 8; r++) { p[r][0] = 0; p[r][1] = 0; p[r][2] = 0; }
#pragma unroll
    for (int mf = 0; mf < 4; mf++)
#pragma unroll
        for (int nf = 0; nf < 4; nf++) {
            const int col0 = n0 + nf * 8 + tq * 2, col1 = col0 + 1;
            float y00 = fmaxf(acc[mf][nf][0], 0.0f);
            float y01 = fmaxf(acc[mf][nf][1], 0.0f);
            float y10 = fmaxf(acc[mf][nf][2], 0.0f);
            float y11 = fmaxf(acc[mf][nf][3], 0.0f);
#pragma unroll
            for (int ch = 0; ch < 3; ch++) {
                float w0 = s_rw[col0 * 3 + ch], w1 = s_rw[col1 * 3 + ch];
                p[mf * 2 + 0][ch] += y00 * w0 + y01 * w1;
                p[mf * 2 + 1][ch] += y10 * w0 + y11 * w1;
            }
        }
#pragma unroll
    for (int r = 0; r < 8; r++)
#pragma unroll
        for (int ch = 0; ch < 3; ch++) {
            p[r][ch] += __shfl_xor_sync(0xffffffffu, p[r][ch], 1);
            p[r][ch] += __shfl_xor_sync(0xffffffffu, p[r][ch], 2);
        }

    float* part = (float*)(smem + A_SM_OFF);  // [8 wn][128 rows][3]
    __syncthreads();
    if (tq == 0) {
#pragma unroll
        for (int mf = 0; mf < 4; mf++)
#pragma unroll
            for (int h = 0; h < 2; h++) {
                int row = m0 + mf * 16 + g + 8 * h;
                int r = mf * 2 + h;
                part[(wn * 128 + row) * 3 + 0] = p[r][0];
                part[(wn * 128 + row) * 3 + 1] = p[r][1];
                part[(wn * 128 + row) * 3 + 2] = p[r][2];
            }
    }
    __syncthreads();
    if (t < 384) {
        const int m = t / 3, ch = t - m * 3;
        float v = s_rb[ch];
#pragma unroll
        for (int gq = 0; gq < 8; gq++) v += part[(gq * 128 + m) * 3 + ch];
        float sg = 1.0f / (1.0f + expf(-v));
        out_rgb[(base + (size_t)m) * 3 + ch] = sg * 1.002f - 0.001f;
    }
}

// ---------------------------------------------------------------- launch
extern "C" void kernel_launch(void* const* d_in, const int* in_sizes, int n_in,
                              void* d_out, int out_size)
{
    const float*  coords   = (const float*)d_in[0];
    const float*  viewdirs = (const float*)d_in[2];
    const float4* emb      = (const float4*)d_in[3];
    const float*  w1       = (const float*)d_in[4];
    const float*  b1       = (const float*)d_in[5];
    const float*  w2       = (const float*)d_in[6];
    const float*  b2       = (const float*)d_in[7];
    const float*  lin0_w   = (const float*)d_in[8];
    const float*  lin0_b   = (const float*)d_in[9];
    const float*  lin1_w   = (const float*)d_in[10];
    const float*  lin1_b   = (const float*)d_in[11];
    const float*  rgb_w    = (const float*)d_in[12];
    const float*  rgb_b    = (const float*)d_in[13];

    float* dout    = (float*)d_out;
    float* density = dout;
    float* rgb     = dout + NPTS;

    float *feats, *U1T, *U2T;
    __nv_bfloat16 *inp0, *W0T, *W1T;
    cudaGetSymbolAddress((void**)&feats, g_feats);
    cudaGetSymbolAddress((void**)&inp0, g_inp0);
    cudaGetSymbolAddress((void**)&W0T, g_W0T);
    cudaGetSymbolAddress((void**)&W1T, g_W1T);
    cudaGetSymbolAddress((void**)&U1T, g_U1T);
    cudaGetSymbolAddress((void**)&U2T, g_U2T);

    cudaFuncSetAttribute(kernM, cudaFuncAttributeMaxDynamicSharedMemorySize, SMEMM_BYTES);
    cudaFuncSetAttribute(kernB, cudaFuncAttributeMaxDynamicSharedMemorySize, SMEMB_BYTES);

    prepW<<<544, 256>>>(lin0_w, lin1_w, w1, w2, W0T, W1T, U1T, U2T);
    kernA<<<NPTS / 256, 256>>>(coords, emb, feats);
    kernM<<<NTILES, 256, SMEMM_BYTES>>>(feats, viewdirs, U1T, U2T, b1, b2,
                                        density, inp0);
    kernB<<<NTILES, 512, SMEMB_BYTES>>>(inp0, W0T, W1T, lin0_b, lin1_b,
                                        rgb_w, rgb_b, rgb);
}

// round 6
// speedup vs baseline: 6.5090x; 1.3165x over previous
#include <cuda_runtime.h>
#include <cuda_bf16.h>
#include <math.h>
#include <stdint.h>

// ---------------------------------------------------------------- constants
#define NPTS (4096 * 64)
#define NRAYS 4096
#define HASH_MASK 2097151u
#define P1H 2654435761u
#define P2H 805459861u

#define TILE_M 128
#define NTILES (NPTS / TILE_M)   // 2048
#define K1 288                    // 283 padded

// kernB chunk schedule (K=32 each): 9 (gemm1) + 8 (gemm2 x) + 9 (gemm2 inp)
#define NCHUNK 26

// kernB smem layout (bytes), bf16; 4-stage pipeline, row stride 40 bf16 (80B)
#define XSE 264                              // X panel element stride
#define X_BYTES (128 * XSE * 2)              // 67584
#define A_SM_OFF X_BYTES
#define ABUF_B (128 * 40 * 2)                // 10240
#define W_SM_OFF (A_SM_OFF + 4 * ABUF_B)     // 108544
#define WBUF_B (256 * 40 * 2)                // 20480
#define BIAS_OFF (W_SM_OFF + 4 * WBUF_B)     // 190464
#define SMEMB_BYTES (BIAS_OFF + 5136)        // 195600

// kernM smem layout (floats)
#define M_FEATS 0                 // [128][52]
#define M_H     (128 * 52)        // [128][68]
#define M_U1    (M_H + 128 * 68)  // [64][52]
#define M_U2    (M_U1 + 64 * 52)  // [256][68]
#define M_B1    (M_U2 + 256 * 68)
#define M_B2    (M_B1 + 64)
#define M_DE    (M_B2 + 256)      // [2][32]
#define SMEMM_FLOATS (M_DE + 64)
#define SMEMM_BYTES (SMEMM_FLOATS * 4)

// ---------------------------------------------------------------- globals
__device__ float g_feats[(size_t)NPTS * 40];
__device__ __nv_bfloat16 g_inp0[(size_t)NPTS * K1];  // [N,288] bf16
__device__ __nv_bfloat16 g_W0T[256 * 288];           // lin0_w^T bf16, padded
__device__ __nv_bfloat16 g_W1T[256 * 544];           // lin1_w^T bf16, padded
__device__ float g_U1T[64 * 40];                     // w1^T (tf32)
__device__ float g_U2T[256 * 64];                    // w2^T (tf32)

// ---------------------------------------------------------------- helpers
__device__ __forceinline__ float tf32r(float v) {
    uint32_t u;
    asm("cvt.rna.tf32.f32 %0, %1;" : "=r"(u) : "f"(v));
    return __uint_as_float(u);
}
__device__ __forceinline__ uint32_t bf16pack(float lo, float hi) {
    uint32_t d;
    asm("cvt.rn.bf16x2.f32 %0, %1, %2;" : "=r"(d) : "f"(hi), "f"(lo));
    return d;
}
__device__ __forceinline__ void mma_tf32(float c[4],
    uint32_t a0, uint32_t a1, uint32_t a2, uint32_t a3,
    uint32_t b0, uint32_t b1)
{
    asm volatile(
        "mma.sync.aligned.m16n8k8.row.col.f32.tf32.tf32.f32 "
        "{%0,%1,%2,%3},{%4,%5,%6,%7},{%8,%9},{%0,%1,%2,%3};"
        : "+f"(c[0]), "+f"(c[1]), "+f"(c[2]), "+f"(c[3])
        : "r"(a0), "r"(a1), "r"(a2), "r"(a3), "r"(b0), "r"(b1));
}
__device__ __forceinline__ void mma_bf16(float c[4],
    uint32_t a0, uint32_t a1, uint32_t a2, uint32_t a3,
    uint32_t b0, uint32_t b1)
{
    asm volatile(
        "mma.sync.aligned.m16n8k16.row.col.f32.bf16.bf16.f32 "
        "{%0,%1,%2,%3},{%4,%5,%6,%7},{%8,%9},{%0,%1,%2,%3};"
        : "+f"(c[0]), "+f"(c[1]), "+f"(c[2]), "+f"(c[3])
        : "r"(a0), "r"(a1), "r"(a2), "r"(a3), "r"(b0), "r"(b1));
}
__device__ __forceinline__ uint32_t smem_u32(const void* p) {
    uint32_t a;
    asm("{ .reg .u64 t; cvta.to.shared.u64 t, %1; cvt.u32.u64 %0, t; }"
        : "=r"(a) : "l"(p));
    return a;
}
#define CP16(d, s) asm volatile("cp.async.cg.shared.global [%0], [%1], 16;" :: "r"(d), "l"(s))
#define CPCOMMIT() asm volatile("cp.async.commit_group;")
#define CPWAIT2()  asm volatile("cp.async.wait_group 2;" ::: "memory")
#define CPWAIT0()  asm volatile("cp.async.wait_group 0;" ::: "memory")

// ---------------------------------------------------------------- prepW
__global__ void __launch_bounds__(256) prepW(
    const float* __restrict__ l0, const float* __restrict__ l1,
    const float* __restrict__ w1, const float* __restrict__ w2,
    __nv_bfloat16* __restrict__ W0T, __nv_bfloat16* __restrict__ W1T,
    float* __restrict__ U1T, float* __restrict__ U2T)
{
    int idx = blockIdx.x * 256 + threadIdx.x;
    if (idx < 256 * 288) {
        int n = idx / 288, k = idx % 288;
        W0T[idx] = __float2bfloat16((k < 283) ? l0[k * 256 + n] : 0.0f);
    }
    if (idx < 256 * 544) {
        int n = idx / 544, k = idx % 544;
        W1T[idx] = __float2bfloat16((k < 539) ? l1[k * 256 + n] : 0.0f);
    }
    if (idx < 64 * 40) {
        int n = idx / 40, k = idx % 40;
        U1T[idx] = tf32r(w1[k * 64 + n]);
    }
    if (idx < 256 * 64) {
        int n = idx / 64, k = idx % 64;
        U2T[idx] = tf32r(w2[k * 256 + n]);
    }
}

// ---------------------------------------------------------------- kernel A (gather only)
__global__ void __launch_bounds__(256) kernA(
    const float* __restrict__ coords,
    const float4* __restrict__ emb,
    float* __restrict__ feats)
{
    const int pid = blockIdx.x * 256 + threadIdx.x;

    float cx = coords[pid * 3 + 0];
    float cy = coords[pid * 3 + 1];
    float cz = coords[pid * 3 + 2];
    float nn = sqrtf(cx * cx + cy * cy + cz * cz);
    nn = fmaxf(nn, 1.1920929e-7f);
    if (nn > 1.0f) {
        float sc = 2.0f - 1.0f / nn;
        cx = sc * (cx / nn); cy = sc * (cy / nn); cz = sc * (cz / nn);
    }
    cx *= 0.5f; cy *= 0.5f; cz *= 0.5f;
    const float ux = (cx + 1.0f) * 0.5f;
    const float uy = (cy + 1.0f) * 0.5f;
    const float uz = (cz + 1.0f) * 0.5f;

    const int offs[10] = {0, 4096, 36864, 299008, 2396160,
                          4493312, 6590464, 8687616, 10784768, 12881920};
    float f[40];
#pragma unroll
    for (int i = 0; i < 40; i++) f[i] = 0.0f;

#pragma unroll
    for (int l = 0; l < 10; l++) {
        const int res = 16 << l;
        const float s = (float)res - 1.0f;
        float px = ux * s + 0.5f, py = uy * s + 0.5f, pz = uz * s + 0.5f;
        float gxf = floorf(px), gyf = floorf(py), gzf = floorf(pz);
        float fx = px - gxf, fy = py - gyf, fz = pz - gzf;
        int gx = (int)gxf, gy = (int)gyf, gz = (int)gzf;
#pragma unroll
        for (int c = 0; c < 8; c++) {
            const int b0 = c & 1, b1c = (c >> 1) & 1, b2c = (c >> 2) & 1;
            float w = (b0 ? fx : 1.0f - fx) * (b1c ? fy : 1.0f - fy)
                    * (b2c ? fz : 1.0f - fz);
            int idx;
            if (l < 4) {
                idx = (gx + b0) + (gy + b1c) * res + (gz + b2c) * res * res;
            } else {
                idx = (int)(((uint32_t)(gx + b0)
                           ^ ((uint32_t)(gy + b1c) * P1H)
                           ^ ((uint32_t)(gz + b2c) * P2H)) & HASH_MASK);
            }
            float4 e = __ldg(&emb[offs[l] + idx]);
            f[l * 4 + 0] += w * e.x; f[l * 4 + 1] += w * e.y;
            f[l * 4 + 2] += w * e.z; f[l * 4 + 3] += w * e.w;
        }
    }

    float4* out4 = (float4*)(feats + (size_t)pid * 40);
#pragma unroll
    for (int q = 0; q < 10; q++)
        out4[q] = make_float4(tf32r(f[q * 4]), tf32r(f[q * 4 + 1]),
                              tf32r(f[q * 4 + 2]), tf32r(f[q * 4 + 3]));
}

// ---------------------------------------------------------------- kernel M
__global__ void __launch_bounds__(256, 1) kernM(
    const float* __restrict__ feats,
    const float* __restrict__ viewdirs,
    const float* __restrict__ U1T, const float* __restrict__ U2T,
    const float* __restrict__ b1g, const float* __restrict__ b2g,
    float* __restrict__ density, __nv_bfloat16* __restrict__ inp0)
{
    extern __shared__ float sm[];
    const uint32_t sb = smem_u32(sm);
    const int t = threadIdx.x;
    const int wid = t >> 5, lane = t & 31;
    const int g = lane >> 2, tq = lane & 3;
    const size_t base = (size_t)blockIdx.x * TILE_M;

    for (int i = t; i < 128 * 12; i += 256) {
        int r = i / 12, c = 40 + i % 12;
        sm[M_FEATS + r * 52 + c] = 0.0f;
    }
    for (int i = t; i < 64 * 12; i += 256) {
        int r = i / 12, c = 40 + i % 12;
        sm[M_U1 + r * 52 + c] = 0.0f;
    }
    if (t < 64)  sm[M_B1 + t] = b1g[t];
    sm[M_B2 + t] = b2g[t];
    if (t < 64) {
        int ray = (int)(base >> 6) + (t >> 5);
        int i = t & 31;
        float v = 0.0f;
        if (i < 27) {
            float dx = viewdirs[ray * 3 + 0];
            float dy = viewdirs[ray * 3 + 1];
            float dz = viewdirs[ray * 3 + 2];
            if (i < 3) v = (i == 0) ? dx : ((i == 1) ? dy : dz);
            else {
                int j = i - 3, deg = j / 6, rem = j % 6;
                float d = ((rem % 3) == 0) ? dx : (((rem % 3) == 1) ? dy : dz);
                float xb = d * (float)(1 << deg);
                v = (rem < 3) ? sinf(xb) : sinf(xb + 1.5707964f);
            }
        }
        sm[M_DE + (t >> 5) * 32 + i] = v;
    }

    for (int i = t; i < 128 * 10; i += 256) {
        int r = i / 10, seg = i % 10;
        CP16(sb + (M_FEATS + r * 52 + seg * 4) * 4,
             feats + (base + (size_t)r) * 40 + seg * 4);
    }
    for (int i = t; i < 64 * 10; i += 256) {
        int r = i / 10, seg = i % 10;
        CP16(sb + (M_U1 + r * 52 + seg * 4) * 4, U1T + (size_t)r * 40 + seg * 4);
    }
    for (int i = t; i < 256 * 16; i += 256) {
        int r = i / 16, seg = i % 16;
        CP16(sb + (M_U2 + r * 68 + seg * 4) * 4, U2T + (size_t)r * 64 + seg * 4);
    }
    CPCOMMIT();
    CPWAIT0();
    __syncthreads();

    // GEMM0a: h = relu(feats @ U1 + b1), K=48, N=64
    {
        const int wm4 = wid & 3, wn2 = wid >> 2;
        const int m0 = wm4 * 32, n0 = wn2 * 32;
        float acc0[2][4][4];
#pragma unroll
        for (int mf = 0; mf < 2; mf++)
#pragma unroll
            for (int nf = 0; nf < 4; nf++) {
                int col = n0 + nf * 8 + tq * 2;
                acc0[mf][nf][0] = sm[M_B1 + col];
                acc0[mf][nf][1] = sm[M_B1 + col + 1];
                acc0[mf][nf][2] = sm[M_B1 + col];
                acc0[mf][nf][3] = sm[M_B1 + col + 1];
            }
#pragma unroll
        for (int ks = 0; ks < 6; ks++) {
            const int kk = ks * 8;
            uint32_t a[2][4], b[4][2];
#pragma unroll
            for (int mf = 0; mf < 2; mf++) {
                const int r0 = M_FEATS + (m0 + mf * 16 + g) * 52 + kk + tq;
                a[mf][0] = __float_as_uint(sm[r0]);
                a[mf][1] = __float_as_uint(sm[r0 + 8 * 52]);
                a[mf][2] = __float_as_uint(sm[r0 + 4]);
                a[mf][3] = __float_as_uint(sm[r0 + 8 * 52 + 4]);
            }
#pragma unroll
            for (int nf = 0; nf < 4; nf++) {
                const int rb = M_U1 + (n0 + nf * 8 + g) * 52 + kk + tq;
                b[nf][0] = __float_as_uint(sm[rb]);
                b[nf][1] = __float_as_uint(sm[rb + 4]);
            }
#pragma unroll
            for (int mf = 0; mf < 2; mf++)
#pragma unroll
                for (int nf = 0; nf < 4; nf++)
                    mma_tf32(acc0[mf][nf], a[mf][0], a[mf][1], a[mf][2], a[mf][3],
                             b[nf][0], b[nf][1]);
        }
        __syncthreads();
#pragma unroll
        for (int mf = 0; mf < 2; mf++) {
            const int r0 = m0 + mf * 16 + g;
#pragma unroll
            for (int nf = 0; nf < 4; nf++) {
                const int col = n0 + nf * 8 + tq * 2;
                sm[M_H + r0 * 68 + col]       = tf32r(fmaxf(acc0[mf][nf][0], 0.0f));
                sm[M_H + r0 * 68 + col + 1]   = tf32r(fmaxf(acc0[mf][nf][1], 0.0f));
                sm[M_H + (r0+8) * 68 + col]   = tf32r(fmaxf(acc0[mf][nf][2], 0.0f));
                sm[M_H + (r0+8) * 68 + col+1] = tf32r(fmaxf(acc0[mf][nf][3], 0.0f));
            }
        }
    }
    __syncthreads();

    // GEMM0b: bott = h @ U2 + b2, K=64, N=256
    const int wm = wid & 1, wn = wid >> 1;
    const int m0 = wm * 64, n0w = wn * 64;
    float acc[4][8][4];
#pragma unroll
    for (int mf = 0; mf < 4; mf++)
#pragma unroll
        for (int nf = 0; nf < 8; nf++) {
            int col = n0w + nf * 8 + tq * 2;
            acc[mf][nf][0] = sm[M_B2 + col];
            acc[mf][nf][1] = sm[M_B2 + col + 1];
            acc[mf][nf][2] = sm[M_B2 + col];
            acc[mf][nf][3] = sm[M_B2 + col + 1];
        }
#pragma unroll
    for (int ks = 0; ks < 8; ks++) {
        const int kk = ks * 8;
        uint32_t a[4][4], b[8][2];
#pragma unroll
        for (int mf = 0; mf < 4; mf++) {
            const int r0 = M_H + (m0 + mf * 16 + g) * 68 + kk + tq;
            a[mf][0] = __float_as_uint(sm[r0]);
            a[mf][1] = __float_as_uint(sm[r0 + 8 * 68]);
            a[mf][2] = __float_as_uint(sm[r0 + 4]);
            a[mf][3] = __float_as_uint(sm[r0 + 8 * 68 + 4]);
        }
#pragma unroll
        for (int nf = 0; nf < 8; nf++) {
            const int rb = M_U2 + (n0w + nf * 8 + g) * 68 + kk + tq;
            b[nf][0] = __float_as_uint(sm[rb]);
            b[nf][1] = __float_as_uint(sm[rb + 4]);
        }
#pragma unroll
        for (int mf = 0; mf < 4; mf++)
#pragma unroll
            for (int nf = 0; nf < 8; nf++)
                mma_tf32(acc[mf][nf], a[mf][0], a[mf][1], a[mf][2], a[mf][3],
                         b[nf][0], b[nf][1]);
    }

#pragma unroll
    for (int mf = 0; mf < 4; mf++) {
        const int r0 = m0 + mf * 16 + g;
#pragma unroll
        for (int nf = 0; nf < 8; nf++) {
            const int col = n0w + nf * 8 + tq * 2;
            uint32_t v0 = bf16pack(acc[mf][nf][0], acc[mf][nf][1]);
            uint32_t v1 = bf16pack(acc[mf][nf][2], acc[mf][nf][3]);
            *(uint32_t*)(inp0 + (base + (size_t)r0) * K1 + col)       = v0;
            *(uint32_t*)(inp0 + (base + (size_t)(r0 + 8)) * K1 + col) = v1;
        }
        if (wn == 0 && tq == 0) {
            float r = acc[mf][0][0] - 1.0f;
            density[base + r0] = (r > 0.0f) ? (r + log1pf(expf(-r))) : log1pf(expf(r));
            r = acc[mf][0][2] - 1.0f;
            density[base + r0 + 8] = (r > 0.0f) ? (r + log1pf(expf(-r))) : log1pf(expf(r));
        }
    }
#pragma unroll
    for (int j = 0; j < 8; j++) {
        int i = t + 256 * j;
        int row = i >> 4, q = i & 15;
        const float* de = &sm[M_DE + (row >> 6) * 32];
        uint32_t v = bf16pack(de[q * 2], de[q * 2 + 1]);
        *(uint32_t*)(inp0 + (base + (size_t)row) * K1 + 256 + q * 2) = v;
    }
}

// ---------------------------------------------------------------- kernel B (bf16 mma)
// 512 threads, 16 warps: warp grid 2(M) x 8(N), warp tile 64x32, CTA tile 128x256
// K=32 chunks, 4-stage cp.async pipeline, 1 barrier per chunk.
__device__ __forceinline__ void gemm_k32(
    const __nv_bfloat16* __restrict__ As, int saE, int koffE,
    const __nv_bfloat16* __restrict__ Ws,
    int m0, int n0, int g, int tq, float acc[4][4][4])
{
#pragma unroll
    for (int ks = 0; ks < 2; ks++) {
        const int ke = koffE + ks * 16;
        uint32_t a[4][4], b[4][2];
#pragma unroll
        for (int mf = 0; mf < 4; mf++) {
            const __nv_bfloat16* ap = As + (m0 + mf * 16 + g) * saE + ke + tq * 2;
            a[mf][0] = *(const uint32_t*)ap;
            a[mf][1] = *(const uint32_t*)(ap + 8 * saE);
            a[mf][2] = *(const uint32_t*)(ap + 8);
            a[mf][3] = *(const uint32_t*)(ap + 8 * saE + 8);
        }
#pragma unroll
        for (int nf = 0; nf < 4; nf++) {
            const __nv_bfloat16* bp = Ws + (n0 + nf * 8 + g) * 40 + ks * 16 + tq * 2;
            b[nf][0] = *(const uint32_t*)bp;
            b[nf][1] = *(const uint32_t*)(bp + 8);
        }
#pragma unroll
        for (int mf = 0; mf < 4; mf++)
#pragma unroll
            for (int nf = 0; nf < 4; nf++)
                mma_bf16(acc[mf][nf], a[mf][0], a[mf][1], a[mf][2], a[mf][3],
                         b[nf][0], b[nf][1]);
    }
}

__global__ void __launch_bounds__(512, 1) kernB(
    const __nv_bfloat16* __restrict__ inp0,
    const __nv_bfloat16* __restrict__ W0T, const __nv_bfloat16* __restrict__ W1T,
    const float* __restrict__ b0g, const float* __restrict__ b1g,
    const float* __restrict__ rgbwg, const float* __restrict__ rgbbg,
    float* __restrict__ out_rgb)
{
    extern __shared__ char smem[];
    __nv_bfloat16* Xs = (__nv_bfloat16*)smem;         // [128][264] bf16
    float* s_b0 = (float*)(smem + BIAS_OFF);
    float* s_b1 = (float*)(smem + BIAS_OFF + 1024);
    float* s_rw = (float*)(smem + BIAS_OFF + 2048);
    float* s_rb = (float*)(smem + BIAS_OFF + 5120);
    const uint32_t sb = smem_u32(smem);

    const int t = threadIdx.x;
    const int wid = t >> 5, lane = t & 31;
    const int g = lane >> 2, tq = lane & 3;
    const int wm = wid & 1, wn = wid >> 1;
    const int m0 = wm * 64, n0 = wn * 32;
    const size_t base = (size_t)blockIdx.x * TILE_M;

    if (t < 256) { s_b0[t] = b0g[t]; s_b1[t] = b1g[t]; }
    for (int i = t; i < 768; i += 512) s_rw[i] = rgbwg[i];
    if (t < 3) s_rb[t] = rgbbg[t];
    __syncthreads();

    auto issue_load = [&](int p) {
        const uint32_t abase = sb + A_SM_OFF + (uint32_t)(p & 3) * ABUF_B;
        const uint32_t wbase = sb + W_SM_OFF + (uint32_t)(p & 3) * WBUF_B;
        const __nv_bfloat16* wsrc; int wld, wcol, acol; bool hasA;
        if (p < 9)       { wsrc = W0T; wld = 288; wcol = p * 32; hasA = true;  acol = p * 32; }
        else if (p < 17) { wsrc = W1T; wld = 544; wcol = (p - 9) * 32; hasA = false; acol = 0; }
        else             { wsrc = W1T; wld = 544; wcol = 256 + (p - 17) * 32; hasA = true; acol = (p - 17) * 32; }
#pragma unroll
        for (int j = 0; j < 2; j++) {   // 256 rows x 4 segs of 16B
            int i = t + 512 * j, row = i >> 2, seg = i & 3;
            CP16(wbase + (uint32_t)row * 80u + (uint32_t)seg * 16u,
                 wsrc + (size_t)row * wld + wcol + seg * 8);
        }
        if (hasA) {                     // 128 rows x 4 segs
            int row = t >> 2, seg = t & 3;
            CP16(abase + (uint32_t)row * 80u + (uint32_t)seg * 16u,
                 inp0 + (base + (size_t)row) * K1 + acol + seg * 8);
        }
    };

    float acc[4][4][4];
#pragma unroll
    for (int mf = 0; mf < 4; mf++)
#pragma unroll
        for (int nf = 0; nf < 4; nf++) {
            int col = n0 + nf * 8 + tq * 2;
            acc[mf][nf][0] = s_b0[col];
            acc[mf][nf][1] = s_b0[col + 1];
            acc[mf][nf][2] = s_b0[col];
            acc[mf][nf][3] = s_b0[col + 1];
        }

    issue_load(0); CPCOMMIT();
    issue_load(1); CPCOMMIT();
    issue_load(2); CPCOMMIT();

    for (int c = 0; c < NCHUNK; c++) {
        CPWAIT2();
        __syncthreads();

        const __nv_bfloat16* Ws =
            (const __nv_bfloat16*)(smem + W_SM_OFF + (c & 3) * WBUF_B);
        if (c >= 9 && c < 17) {
            gemm_k32(Xs, XSE, (c - 9) * 32, Ws, m0, n0, g, tq, acc);
        } else {
            const __nv_bfloat16* As =
                (const __nv_bfloat16*)(smem + A_SM_OFF + (c & 3) * ABUF_B);
            gemm_k32(As, 40, 0, Ws, m0, n0, g, tq, acc);
        }

        if (c == 8) {
            // epilogue 1: relu(x + b0) -> bf16 -> X panel; reset acc to b1.
            // X is first read at c==9, after the top-of-iteration barrier.
#pragma unroll
            for (int mf = 0; mf < 4; mf++) {
                const int r0 = m0 + mf * 16 + g;
#pragma unroll
                for (int nf = 0; nf < 4; nf++) {
                    const int col = n0 + nf * 8 + tq * 2;
                    uint32_t v0 = bf16pack(fmaxf(acc[mf][nf][0], 0.0f),
                                           fmaxf(acc[mf][nf][1], 0.0f));
                    uint32_t v1 = bf16pack(fmaxf(acc[mf][nf][2], 0.0f),
                                           fmaxf(acc[mf][nf][3], 0.0f));
                    *(uint32_t*)(Xs + r0 * XSE + col)       = v0;
                    *(uint32_t*)(Xs + (r0 + 8) * XSE + col) = v1;
                    acc[mf][nf][0] = s_b1[col];
                    acc[mf][nf][1] = s_b1[col + 1];
                    acc[mf][nf][2] = s_b1[col];
                    acc[mf][nf][3] = s_b1[col + 1];
                }
            }
        }
        if (c + 3 < NCHUNK) issue_load(c + 3);
        CPCOMMIT();
    }

    // ---------------- rgb head ----------------
    float p[8][3];
#pragma unroll
    for (int r = 0; r < 8; r++) { p[r][0] = 0; p[r][1] = 0; p[r][2] = 0; }
#pragma unroll
    for (int mf = 0; mf < 4; mf++)
#pragma unroll
        for (int nf = 0; nf < 4; nf++) {
            const int col0 = n0 + nf * 8 + tq * 2, col1 = col0 + 1;
            float y00 = fmaxf(acc[mf][nf][0], 0.0f);
            float y01 = fmaxf(acc[mf][nf][1], 0.0f);
            float y10 = fmaxf(acc[mf][nf][2], 0.0f);
            float y11 = fmaxf(acc[mf][nf][3], 0.0f);
#pragma unroll
            for (int ch = 0; ch < 3; ch++) {
                float w0 = s_rw[col0 * 3 + ch], w1 = s_rw[col1 * 3 + ch];
                p[mf * 2 + 0][ch] += y00 * w0 + y01 * w1;
                p[mf * 2 + 1][ch] += y10 * w0 + y11 * w1;
            }
        }
#pragma unroll
    for (int r = 0; r < 8; r++)
#pragma unroll
        for (int ch = 0; ch < 3; ch++) {
            p[r][ch] += __shfl_xor_sync(0xffffffffu, p[r][ch], 1);
            p[r][ch] += __shfl_xor_sync(0xffffffffu, p[r][ch], 2);
        }

    float* part = (float*)(smem + A_SM_OFF);  // [8 wn][128 rows][3]
    __syncthreads();
    if (tq == 0) {
#pragma unroll
        for (int mf = 0; mf < 4; mf++)
#pragma unroll
            for (int h = 0; h < 2; h++) {
                int row = m0 + mf * 16 + g + 8 * h;
                int r = mf * 2 + h;
                part[(wn * 128 + row) * 3 + 0] = p[r][0];
                part[(wn * 128 + row) * 3 + 1] = p[r][1];
                part[(wn * 128 + row) * 3 + 2] = p[r][2];
            }
    }
    __syncthreads();
    if (t < 384) {
        const int m = t / 3, ch = t - m * 3;
        float v = s_rb[ch];
#pragma unroll
        for (int gq = 0; gq < 8; gq++) v += part[(gq * 128 + m) * 3 + ch];
        float sg = 1.0f / (1.0f + expf(-v));
        out_rgb[(base + (size_t)m) * 3 + ch] = sg * 1.002f - 0.001f;
    }
}

// ---------------------------------------------------------------- launch
extern "C" void kernel_launch(void* const* d_in, const int* in_sizes, int n_in,
                              void* d_out, int out_size)
{
    const float*  coords   = (const float*)d_in[0];
    const float*  viewdirs = (const float*)d_in[2];
    const float4* emb      = (const float4*)d_in[3];
    const float*  w1       = (const float*)d_in[4];
    const float*  b1       = (const float*)d_in[5];
    const float*  w2       = (const float*)d_in[6];
    const float*  b2       = (const float*)d_in[7];
    const float*  lin0_w   = (const float*)d_in[8];
    const float*  lin0_b   = (const float*)d_in[9];
    const float*  lin1_w   = (const float*)d_in[10];
    const float*  lin1_b   = (const float*)d_in[11];
    const float*  rgb_w    = (const float*)d_in[12];
    const float*  rgb_b    = (const float*)d_in[13];

    float* dout    = (float*)d_out;
    float* density = dout;
    float* rgb     = dout + NPTS;

    float *feats, *U1T, *U2T;
    __nv_bfloat16 *inp0, *W0T, *W1T;
    cudaGetSymbolAddress((void**)&feats, g_feats);
    cudaGetSymbolAddress((void**)&inp0, g_inp0);
    cudaGetSymbolAddress((void**)&W0T, g_W0T);
    cudaGetSymbolAddress((void**)&W1T, g_W1T);
    cudaGetSymbolAddress((void**)&U1T, g_U1T);
    cudaGetSymbolAddress((void**)&U2T, g_U2T);

    cudaFuncSetAttribute(kernM, cudaFuncAttributeMaxDynamicSharedMemorySize, SMEMM_BYTES);
    cudaFuncSetAttribute(kernB, cudaFuncAttributeMaxDynamicSharedMemorySize, SMEMB_BYTES);

    prepW<<<544, 256>>>(lin0_w, lin1_w, w1, w2, W0T, W1T, U1T, U2T);
    kernA<<<NPTS / 256, 256>>>(coords, emb, feats);
    kernM<<<NTILES, 256, SMEMM_BYTES>>>(feats, viewdirs, U1T, U2T, b1, b2,
                                        density, inp0);
    kernB<<<NTILES, 512, SMEMB_BYTES>>>(inp0, W0T, W1T, lin0_b, lin1_b,
                                        rgb_w, rgb_b, rgb);
}

// round 7
// speedup vs baseline: 7.7115x; 1.1848x over previous
#include <cuda_runtime.h>
#include <cuda_bf16.h>
#include <math.h>
#include <stdint.h>

// ---------------------------------------------------------------- constants
#define NPTS (4096 * 64)
#define NRAYS 4096
#define HASH_MASK 2097151u
#define P1H 2654435761u
#define P2H 805459861u

#define TILE_M 128
#define NTILES (NPTS / TILE_M)   // 2048
#define NCHUNK 26                 // 9 (gemm1 K=288) + 8 (gemm2 X K=256) + 9 (gemm2 bott K=288)

// ---------------- fused kernel smem layout (bytes) ----------------
// X panel:    bf16 [128][296] @0          (75776)   alias: U2 fp32 [256][68] (69632)
// BOTT panel: bf16 [128][296] @75776      (75776)   alias: FE fp32[128][52]@+0 (26624),
//                                                          H fp32[128][68]@+26624 (34816),
//                                                          U1 fp32[64][52]@+61440 (13312)
// W stream:   3 x bf16 [256][40] @151552  (61440)
// BIAS:       @212992 floats: sb1[64] sb2[256] b0[256] b1[256] rgbw[768] rgbb[4] sDE[64]
#define SB_X    0
#define U2_OFF  0
#define SB_BOTT 75776
#define FE_OFF  75776
#define H_OFF   102400
#define U1_OFF  137216
#define SB_W    151552
#define WBUF_B  20480
#define SB_BIAS 212992
#define SMEMF_BYTES (SB_BIAS + 6672)    // 219664

// bias-region float indices
#define BI_SB1  0
#define BI_SB2  64
#define BI_B0   320
#define BI_B1   576
#define BI_RW   832
#define BI_RB   1600
#define BI_DE   1604

// ---------------------------------------------------------------- globals
__device__ float g_feats[(size_t)NPTS * 40];
__device__ __nv_bfloat16 g_W0T[256 * 288];   // lin0_w^T bf16, padded
__device__ __nv_bfloat16 g_W1T[256 * 544];   // lin1_w^T bf16, padded
__device__ float g_U1T[64 * 40];             // w1^T (tf32)
__device__ float g_U2T[256 * 64];            // w2^T (tf32)

// ---------------------------------------------------------------- helpers
__device__ __forceinline__ float tf32r(float v) {
    uint32_t u;
    asm("cvt.rna.tf32.f32 %0, %1;" : "=r"(u) : "f"(v));
    return __uint_as_float(u);
}
__device__ __forceinline__ uint32_t bf16pack(float lo, float hi) {
    uint32_t d;
    asm("cvt.rn.bf16x2.f32 %0, %1, %2;" : "=r"(d) : "f"(hi), "f"(lo));
    return d;
}
__device__ __forceinline__ void mma_tf32(float c[4],
    uint32_t a0, uint32_t a1, uint32_t a2, uint32_t a3,
    uint32_t b0, uint32_t b1)
{
    asm volatile(
        "mma.sync.aligned.m16n8k8.row.col.f32.tf32.tf32.f32 "
        "{%0,%1,%2,%3},{%4,%5,%6,%7},{%8,%9},{%0,%1,%2,%3};"
        : "+f"(c[0]), "+f"(c[1]), "+f"(c[2]), "+f"(c[3])
        : "r"(a0), "r"(a1), "r"(a2), "r"(a3), "r"(b0), "r"(b1));
}
__device__ __forceinline__ void mma_bf16(float c[4],
    uint32_t a0, uint32_t a1, uint32_t a2, uint32_t a3,
    uint32_t b0, uint32_t b1)
{
    asm volatile(
        "mma.sync.aligned.m16n8k16.row.col.f32.bf16.bf16.f32 "
        "{%0,%1,%2,%3},{%4,%5,%6,%7},{%8,%9},{%0,%1,%2,%3};"
        : "+f"(c[0]), "+f"(c[1]), "+f"(c[2]), "+f"(c[3])
        : "r"(a0), "r"(a1), "r"(a2), "r"(a3), "r"(b0), "r"(b1));
}
#define LDSM4(r, a) \
    asm volatile("ldmatrix.sync.aligned.m8n8.x4.shared.b16 {%0,%1,%2,%3}, [%4];" \
        : "=r"((r)[0]), "=r"((r)[1]), "=r"((r)[2]), "=r"((r)[3]) : "r"(a))
__device__ __forceinline__ uint32_t smem_u32(const void* p) {
    uint32_t a;
    asm("{ .reg .u64 t; cvta.to.shared.u64 t, %1; cvt.u32.u64 %0, t; }"
        : "=r"(a) : "l"(p));
    return a;
}
#define CP16(d, s) asm volatile("cp.async.cg.shared.global [%0], [%1], 16;" :: "r"(d), "l"(s))
#define CPCOMMIT() asm volatile("cp.async.commit_group;")
#define CPWAIT2()  asm volatile("cp.async.wait_group 2;" ::: "memory")
#define CPWAIT1()  asm volatile("cp.async.wait_group 1;" ::: "memory")
#define CPWAIT0()  asm volatile("cp.async.wait_group 0;" ::: "memory")
#define STS_ZERO16(a) asm volatile("st.shared.v4.u32 [%0], {%1,%1,%1,%1};" :: "r"(a), "r"(0u) : "memory")

// ---------------------------------------------------------------- prepW
__global__ void __launch_bounds__(256) prepW(
    const float* __restrict__ l0, const float* __restrict__ l1,
    const float* __restrict__ w1, const float* __restrict__ w2,
    __nv_bfloat16* __restrict__ W0T, __nv_bfloat16* __restrict__ W1T,
    float* __restrict__ U1T, float* __restrict__ U2T)
{
    int idx = blockIdx.x * 256 + threadIdx.x;
    if (idx < 256 * 288) {
        int n = idx / 288, k = idx % 288;
        W0T[idx] = __float2bfloat16((k < 283) ? l0[k * 256 + n] : 0.0f);
    }
    if (idx < 256 * 544) {
        int n = idx / 544, k = idx % 544;
        W1T[idx] = __float2bfloat16((k < 539) ? l1[k * 256 + n] : 0.0f);
    }
    if (idx < 64 * 40) {
        int n = idx / 40, k = idx % 40;
        U1T[idx] = tf32r(w1[k * 64 + n]);
    }
    if (idx < 256 * 64) {
        int n = idx / 64, k = idx % 64;
        U2T[idx] = tf32r(w2[k * 256 + n]);
    }
}

// ---------------------------------------------------------------- kernel A (gather only)
__global__ void __launch_bounds__(256) kernA(
    const float* __restrict__ coords,
    const float4* __restrict__ emb,
    float* __restrict__ feats)
{
    const int pid = blockIdx.x * 256 + threadIdx.x;

    float cx = coords[pid * 3 + 0];
    float cy = coords[pid * 3 + 1];
    float cz = coords[pid * 3 + 2];
    float nn = sqrtf(cx * cx + cy * cy + cz * cz);
    nn = fmaxf(nn, 1.1920929e-7f);
    if (nn > 1.0f) {
        float sc = 2.0f - 1.0f / nn;
        cx = sc * (cx / nn); cy = sc * (cy / nn); cz = sc * (cz / nn);
    }
    cx *= 0.5f; cy *= 0.5f; cz *= 0.5f;
    const float ux = (cx + 1.0f) * 0.5f;
    const float uy = (cy + 1.0f) * 0.5f;
    const float uz = (cz + 1.0f) * 0.5f;

    const int offs[10] = {0, 4096, 36864, 299008, 2396160,
                          4493312, 6590464, 8687616, 10784768, 12881920};
    float f[40];
#pragma unroll
    for (int i = 0; i < 40; i++) f[i] = 0.0f;

#pragma unroll
    for (int l = 0; l < 10; l++) {
        const int res = 16 << l;
        const float s = (float)res - 1.0f;
        float px = ux * s + 0.5f, py = uy * s + 0.5f, pz = uz * s + 0.5f;
        float gxf = floorf(px), gyf = floorf(py), gzf = floorf(pz);
        float fx = px - gxf, fy = py - gyf, fz = pz - gzf;
        int gx = (int)gxf, gy = (int)gyf, gz = (int)gzf;
#pragma unroll
        for (int c = 0; c < 8; c++) {
            const int b0 = c & 1, b1c = (c >> 1) & 1, b2c = (c >> 2) & 1;
            float w = (b0 ? fx : 1.0f - fx) * (b1c ? fy : 1.0f - fy)
                    * (b2c ? fz : 1.0f - fz);
            int idx;
            if (l < 4) {
                idx = (gx + b0) + (gy + b1c) * res + (gz + b2c) * res * res;
            } else {
                idx = (int)(((uint32_t)(gx + b0)
                           ^ ((uint32_t)(gy + b1c) * P1H)
                           ^ ((uint32_t)(gz + b2c) * P2H)) & HASH_MASK);
            }
            float4 e = __ldg(&emb[offs[l] + idx]);
            f[l * 4 + 0] += w * e.x; f[l * 4 + 1] += w * e.y;
            f[l * 4 + 2] += w * e.z; f[l * 4 + 3] += w * e.w;
        }
    }

    float4* out4 = (float4*)(feats + (size_t)pid * 40);
#pragma unroll
    for (int q = 0; q < 10; q++)
        out4[q] = make_float4(tf32r(f[q * 4]), tf32r(f[q * 4 + 1]),
                              tf32r(f[q * 4 + 2]), tf32r(f[q * 4 + 3]));
}

// ---------------------------------------------------------------- fused kernel
// 512 threads, 16 warps. Phases:
//  0: cp.async feats/U1/U2 (+W0,W1 prefetch); plain sts for pads/dirs/biases
//  1: GEMM0a (tf32): h = relu(feats@U1+b1), fp32 smem
//  2: GEMM0b (tf32): bott = h@U2+b2 -> BOTT panel bf16 (+density, +direnc)
//  3: main loop, 26 W-chunks (bf16 mma + ldmatrix), A panels resident
//  4: rgb head
__global__ void __launch_bounds__(512, 1) kernF(
    const float* __restrict__ feats,
    const float* __restrict__ viewdirs,
    const float* __restrict__ U1Tg, const float* __restrict__ U2Tg,
    const float* __restrict__ sb1g, const float* __restrict__ sb2g,
    const __nv_bfloat16* __restrict__ W0T, const __nv_bfloat16* __restrict__ W1T,
    const float* __restrict__ b0g, const float* __restrict__ b1g,
    const float* __restrict__ rgbwg, const float* __restrict__ rgbbg,
    float* __restrict__ density, float* __restrict__ out_rgb)
{
    extern __shared__ char smem[];
    const uint32_t sb = smem_u32(smem);
    float* bias = (float*)(smem + SB_BIAS);
    float* FE = (float*)(smem + FE_OFF);    // [128][52]
    float* H  = (float*)(smem + H_OFF);     // [128][68]
    float* U1 = (float*)(smem + U1_OFF);    // [64][52]
    float* U2 = (float*)(smem + U2_OFF);    // [256][68]
    __nv_bfloat16* Xp = (__nv_bfloat16*)(smem + SB_X);     // [128][296]
    __nv_bfloat16* Bp = (__nv_bfloat16*)(smem + SB_BOTT);  // [128][296]

    const int t = threadIdx.x;
    const int wid = t >> 5, lane = t & 31;
    const int g = lane >> 2, tq = lane & 3;
    const size_t base = (size_t)blockIdx.x * TILE_M;

    // ---- phase 0: small data + pads (plain stores) ----
    if (t < 64)  bias[BI_SB1 + t] = sb1g[t];
    if (t >= 64 && t < 320) bias[BI_SB2 + t - 64] = sb2g[t - 64];
    if (t < 256) { bias[BI_B0 + t] = b0g[t]; bias[BI_B1 + t] = b1g[t]; }
    for (int i = t; i < 768; i += 512) bias[BI_RW + i] = rgbwg[i];
    if (t < 3) bias[BI_RB + t] = rgbbg[t];
    if (t < 64) {   // direnc for the tile's 2 rays
        int ray = (int)(base >> 6) + (t >> 5);
        int i = t & 31;
        float v = 0.0f;
        if (i < 27) {
            float dx = viewdirs[ray * 3 + 0];
            float dy = viewdirs[ray * 3 + 1];
            float dz = viewdirs[ray * 3 + 2];
            if (i < 3) v = (i == 0) ? dx : ((i == 1) ? dy : dz);
            else {
                int j = i - 3, deg = j / 6, rem = j % 6;
                float d = ((rem % 3) == 0) ? dx : (((rem % 3) == 1) ? dy : dz);
                float xb = d * (float)(1 << deg);
                v = (rem < 3) ? sinf(xb) : sinf(xb + 1.5707964f);
            }
        }
        bias[BI_DE + (t >> 5) * 32 + i] = v;
    }
    // zero pads: FE cols 40-51 (3x16B/row), U1 cols 40-51
    for (int i = t; i < 128 * 3; i += 512) {
        int r = i / 3, s = i % 3;
        STS_ZERO16(sb + FE_OFF + (uint32_t)(r * 208 + 160 + s * 16));
    }
    for (int i = t; i < 64 * 3; i += 512) {
        int r = i / 3, s = i % 3;
        STS_ZERO16(sb + U1_OFF + (uint32_t)(r * 208 + 160 + s * 16));
    }
    // ---- phase 0: cp.async group G0 ----
    for (int i = t; i < 128 * 10; i += 512) {
        int r = i / 10, s = i % 10;
        CP16(sb + FE_OFF + (uint32_t)(r * 208 + s * 16),
             feats + (base + (size_t)r) * 40 + s * 4);
    }
    for (int i = t; i < 64 * 10; i += 512) {
        int r = i / 10, s = i % 10;
        CP16(sb + U1_OFF + (uint32_t)(r * 208 + s * 16), U1Tg + (size_t)r * 40 + s * 4);
    }
#pragma unroll
    for (int j = 0; j < 8; j++) {   // U2: 256 rows x 16 segs
        int i = t + 512 * j;
        int r = i >> 4, s = i & 15;
        CP16(sb + U2_OFF + (uint32_t)(r * 272 + s * 16), U2Tg + (size_t)r * 64 + s * 4);
    }
    CPCOMMIT();

    auto issueW = [&](int p) {
        const uint32_t wbase = sb + SB_W + (uint32_t)(p % 3) * WBUF_B;
        const __nv_bfloat16* wsrc; int wld, wcol;
        if (p < 9)       { wsrc = W0T; wld = 288; wcol = p * 32; }
        else if (p < 17) { wsrc = W1T; wld = 544; wcol = (p - 9) * 32; }
        else             { wsrc = W1T; wld = 544; wcol = 256 + (p - 17) * 32; }
#pragma unroll
        for (int j = 0; j < 2; j++) {   // 256 rows x 4 segs of 16B
            int i = t + 512 * j, row = i >> 2, seg = i & 3;
            CP16(wbase + (uint32_t)row * 80u + (uint32_t)seg * 16u,
                 wsrc + (size_t)row * wld + wcol + seg * 8);
        }
    };
    issueW(0); CPCOMMIT();
    issueW(1); CPCOMMIT();

    CPWAIT2();      // G0 done (W0, W1 may be in flight)
    __syncthreads();

    // ---- phase 1: GEMM0a (tf32): h = relu(feats @ U1 + sb1), K=48, N=64 ----
    {
        const int m0a = (wid & 3) * 32, n0a = (wid >> 2) * 16;
        float acc0[2][2][4];
#pragma unroll
        for (int mf = 0; mf < 2; mf++)
#pragma unroll
            for (int nf = 0; nf < 2; nf++) {
                int col = n0a + nf * 8 + tq * 2;
                acc0[mf][nf][0] = bias[BI_SB1 + col];
                acc0[mf][nf][1] = bias[BI_SB1 + col + 1];
                acc0[mf][nf][2] = bias[BI_SB1 + col];
                acc0[mf][nf][3] = bias[BI_SB1 + col + 1];
            }
#pragma unroll
        for (int ks = 0; ks < 6; ks++) {
            const int kk = ks * 8;
            uint32_t a[2][4], b[2][2];
#pragma unroll
            for (int mf = 0; mf < 2; mf++) {
                const int r0 = (m0a + mf * 16 + g) * 52 + kk + tq;
                a[mf][0] = __float_as_uint(FE[r0]);
                a[mf][1] = __float_as_uint(FE[r0 + 8 * 52]);
                a[mf][2] = __float_as_uint(FE[r0 + 4]);
                a[mf][3] = __float_as_uint(FE[r0 + 8 * 52 + 4]);
            }
#pragma unroll
            for (int nf = 0; nf < 2; nf++) {
                const int rb = (n0a + nf * 8 + g) * 52 + kk + tq;
                b[nf][0] = __float_as_uint(U1[rb]);
                b[nf][1] = __float_as_uint(U1[rb + 4]);
            }
#pragma unroll
            for (int mf = 0; mf < 2; mf++)
#pragma unroll
                for (int nf = 0; nf < 2; nf++)
                    mma_tf32(acc0[mf][nf], a[mf][0], a[mf][1], a[mf][2], a[mf][3],
                             b[nf][0], b[nf][1]);
        }
        __syncthreads();   // FE reads done before H writes (H separate, but keep order cheap)
#pragma unroll
        for (int mf = 0; mf < 2; mf++) {
            const int r0 = m0a + mf * 16 + g;
#pragma unroll
            for (int nf = 0; nf < 2; nf++) {
                const int col = n0a + nf * 8 + tq * 2;
                H[r0 * 68 + col]         = tf32r(fmaxf(acc0[mf][nf][0], 0.0f));
                H[r0 * 68 + col + 1]     = tf32r(fmaxf(acc0[mf][nf][1], 0.0f));
                H[(r0 + 8) * 68 + col]   = tf32r(fmaxf(acc0[mf][nf][2], 0.0f));
                H[(r0 + 8) * 68 + col+1] = tf32r(fmaxf(acc0[mf][nf][3], 0.0f));
            }
        }
    }
    __syncthreads();

    // ---- phase 2: GEMM0b (tf32): bott = h @ U2 + sb2 -> BOTT bf16 ----
    const int wm = wid & 1, wn = wid >> 1;
    const int m0 = wm * 64, n0 = wn * 32;
    float acc[4][4][4];
#pragma unroll
    for (int mf = 0; mf < 4; mf++)
#pragma unroll
        for (int nf = 0; nf < 4; nf++) {
            int col = n0 + nf * 8 + tq * 2;
            acc[mf][nf][0] = bias[BI_SB2 + col];
            acc[mf][nf][1] = bias[BI_SB2 + col + 1];
            acc[mf][nf][2] = bias[BI_SB2 + col];
            acc[mf][nf][3] = bias[BI_SB2 + col + 1];
        }
#pragma unroll
    for (int ks = 0; ks < 8; ks++) {
        const int kk = ks * 8;
        uint32_t a[4][4], b[4][2];
#pragma unroll
        for (int mf = 0; mf < 4; mf++) {
            const int r0 = (m0 + mf * 16 + g) * 68 + kk + tq;
            a[mf][0] = __float_as_uint(H[r0]);
            a[mf][1] = __float_as_uint(H[r0 + 8 * 68]);
            a[mf][2] = __float_as_uint(H[r0 + 4]);
            a[mf][3] = __float_as_uint(H[r0 + 8 * 68 + 4]);
        }
#pragma unroll
        for (int nf = 0; nf < 4; nf++) {
            const int rb = (n0 + nf * 8 + g) * 68 + kk + tq;
            b[nf][0] = __float_as_uint(U2[rb]);
            b[nf][1] = __float_as_uint(U2[rb + 4]);
        }
#pragma unroll
        for (int mf = 0; mf < 4; mf++)
#pragma unroll
            for (int nf = 0; nf < 4; nf++)
                mma_tf32(acc[mf][nf], a[mf][0], a[mf][1], a[mf][2], a[mf][3],
                         b[nf][0], b[nf][1]);
    }
    __syncthreads();   // all H/U2 reads done before BOTT (aliases H/FE) is written

    // epilogue 0b: BOTT bf16 cols 0..255 + density; direnc cols 256..287
#pragma unroll
    for (int mf = 0; mf < 4; mf++) {
        const int r0 = m0 + mf * 16 + g;
#pragma unroll
        for (int nf = 0; nf < 4; nf++) {
            const int col = n0 + nf * 8 + tq * 2;
            *(uint32_t*)(Bp + r0 * 296 + col)       = bf16pack(acc[mf][nf][0], acc[mf][nf][1]);
            *(uint32_t*)(Bp + (r0 + 8) * 296 + col) = bf16pack(acc[mf][nf][2], acc[mf][nf][3]);
        }
        if (wn == 0 && tq == 0) {
            float r = acc[mf][0][0] - 1.0f;
            density[base + r0] = (r > 0.0f) ? (r + log1pf(expf(-r))) : log1pf(expf(r));
            r = acc[mf][0][2] - 1.0f;
            density[base + r0 + 8] = (r > 0.0f) ? (r + log1pf(expf(-r))) : log1pf(expf(r));
        }
    }
#pragma unroll
    for (int j = 0; j < 4; j++) {   // 128 rows x 16 bf16 pairs (cols 256..287; 27 real + 5 zero)
        int i = t + 512 * j;
        int row = i >> 4, q = i & 15;
        const float* de = &bias[BI_DE + (row >> 6) * 32];
        *(uint32_t*)(Bp + row * 296 + 256 + q * 2) = bf16pack(de[q * 2], de[q * 2 + 1]);
    }

    // re-init acc with b0 for GEMM1
#pragma unroll
    for (int mf = 0; mf < 4; mf++)
#pragma unroll
        for (int nf = 0; nf < 4; nf++) {
            int col = n0 + nf * 8 + tq * 2;
            acc[mf][nf][0] = bias[BI_B0 + col];
            acc[mf][nf][1] = bias[BI_B0 + col + 1];
            acc[mf][nf][2] = bias[BI_B0 + col];
            acc[mf][nf][3] = bias[BI_B0 + col + 1];
        }

    // ---- phase 3: main loop, 26 chunks ----
    const int arow = lane & 15;
    const int ak8  = ((lane >> 4) & 1) << 3;
    const int brow = ((lane >> 1) & 8) + (lane & 7);
    const int bk8  = lane & 8;

    for (int c = 0; c < NCHUNK; c++) {
        if (c + 1 < NCHUNK) { CPWAIT1(); } else { CPWAIT0(); }
        __syncthreads();

        uint32_t aPane; int k0;
        if (c < 9)       { aPane = sb + SB_BOTT; k0 = c * 32; }
        else if (c < 17) { aPane = sb + SB_X;    k0 = (c - 9) * 32; }
        else             { aPane = sb + SB_BOTT; k0 = (c - 17) * 32; }
        const uint32_t wPane = sb + SB_W + (uint32_t)(c % 3) * WBUF_B;

#pragma unroll
        for (int ks = 0; ks < 2; ks++) {
            const int kk = k0 + ks * 16;
            uint32_t a[4][4], bb[2][4];
#pragma unroll
            for (int mf = 0; mf < 4; mf++) {
                uint32_t addr = aPane +
                    (uint32_t)(((m0 + mf * 16 + arow) * 296) + kk + ak8) * 2u;
                LDSM4(a[mf], addr);
            }
#pragma unroll
            for (int p = 0; p < 2; p++) {
                uint32_t addr = wPane +
                    (uint32_t)(((n0 + p * 16 + brow) * 40) + ks * 16 + bk8) * 2u;
                LDSM4(bb[p], addr);
            }
#pragma unroll
            for (int mf = 0; mf < 4; mf++)
#pragma unroll
                for (int p = 0; p < 2; p++) {
                    mma_bf16(acc[mf][p * 2 + 0], a[mf][0], a[mf][1], a[mf][2], a[mf][3],
                             bb[p][0], bb[p][1]);
                    mma_bf16(acc[mf][p * 2 + 1], a[mf][0], a[mf][1], a[mf][2], a[mf][3],
                             bb[p][2], bb[p][3]);
                }
        }

        if (c == 8) {
            // epilogue 1: relu(x + b0) -> bf16 -> X panel; reset acc to b1.
            // X first read at c==9 after the top-of-iteration barrier.
#pragma unroll
            for (int mf = 0; mf < 4; mf++) {
                const int r0 = m0 + mf * 16 + g;
#pragma unroll
                for (int nf = 0; nf < 4; nf++) {
                    const int col = n0 + nf * 8 + tq * 2;
                    *(uint32_t*)(Xp + r0 * 296 + col) =
                        bf16pack(fmaxf(acc[mf][nf][0], 0.0f), fmaxf(acc[mf][nf][1], 0.0f));
                    *(uint32_t*)(Xp + (r0 + 8) * 296 + col) =
                        bf16pack(fmaxf(acc[mf][nf][2], 0.0f), fmaxf(acc[mf][nf][3], 0.0f));
                    acc[mf][nf][0] = bias[BI_B1 + col];
                    acc[mf][nf][1] = bias[BI_B1 + col + 1];
                    acc[mf][nf][2] = bias[BI_B1 + col];
                    acc[mf][nf][3] = bias[BI_B1 + col + 1];
                }
            }
        }
        if (c + 2 < NCHUNK) issueW(c + 2);
        CPCOMMIT();
    }

    // ---- phase 4: rgb head ----
    float p[8][3];
#pragma unroll
    for (int r = 0; r < 8; r++) { p[r][0] = 0; p[r][1] = 0; p[r][2] = 0; }
#pragma unroll
    for (int mf = 0; mf < 4; mf++)
#pragma unroll
        for (int nf = 0; nf < 4; nf++) {
            const int col0 = n0 + nf * 8 + tq * 2, col1 = col0 + 1;
            float y00 = fmaxf(acc[mf][nf][0], 0.0f);
            float y01 = fmaxf(acc[mf][nf][1], 0.0f);
            float y10 = fmaxf(acc[mf][nf][2], 0.0f);
            float y11 = fmaxf(acc[mf][nf][3], 0.0f);
#pragma unroll
            for (int ch = 0; ch < 3; ch++) {
                float w0 = bias[BI_RW + col0 * 3 + ch], w1 = bias[BI_RW + col1 * 3 + ch];
                p[mf * 2 + 0][ch] += y00 * w0 + y01 * w1;
                p[mf * 2 + 1][ch] += y10 * w0 + y11 * w1;
            }
        }
#pragma unroll
    for (int r = 0; r < 8; r++)
#pragma unroll
        for (int ch = 0; ch < 3; ch++) {
            p[r][ch] += __shfl_xor_sync(0xffffffffu, p[r][ch], 1);
            p[r][ch] += __shfl_xor_sync(0xffffffffu, p[r][ch], 2);
        }

    float* part = (float*)(smem + SB_BOTT);  // BOTT dead after last chunk
    __syncthreads();
    if (tq == 0) {
#pragma unroll
        for (int mf = 0; mf < 4; mf++)
#pragma unroll
            for (int h = 0; h < 2; h++) {
                int row = m0 + mf * 16 + g + 8 * h;
                int r = mf * 2 + h;
                part[(wn * 128 + row) * 3 + 0] = p[r][0];
                part[(wn * 128 + row) * 3 + 1] = p[r][1];
                part[(wn * 128 + row) * 3 + 2] = p[r][2];
            }
    }
    __syncthreads();
    if (t < 384) {
        const int m = t / 3, ch = t - m * 3;
        float v = bias[BI_RB + ch];
#pragma unroll
        for (int gq = 0; gq < 8; gq++) v += part[(gq * 128 + m) * 3 + ch];
        float sg = 1.0f / (1.0f + expf(-v));
        out_rgb[(base + (size_t)m) * 3 + ch] = sg * 1.002f - 0.001f;
    }
}

// ---------------------------------------------------------------- launch
extern "C" void kernel_launch(void* const* d_in, const int* in_sizes, int n_in,
                              void* d_out, int out_size)
{
    const float*  coords   = (const float*)d_in[0];
    const float*  viewdirs = (const float*)d_in[2];
    const float4* emb      = (const float4*)d_in[3];
    const float*  w1       = (const float*)d_in[4];
    const float*  b1       = (const float*)d_in[5];
    const float*  w2       = (const float*)d_in[6];
    const float*  b2       = (const float*)d_in[7];
    const float*  lin0_w   = (const float*)d_in[8];
    const float*  lin0_b   = (const float*)d_in[9];
    const float*  lin1_w   = (const float*)d_in[10];
    const float*  lin1_b   = (const float*)d_in[11];
    const float*  rgb_w    = (const float*)d_in[12];
    const float*  rgb_b    = (const float*)d_in[13];

    float* dout    = (float*)d_out;
    float* density = dout;
    float* rgb     = dout + NPTS;

    float *feats, *U1T, *U2T;
    __nv_bfloat16 *W0T, *W1T;
    cudaGetSymbolAddress((void**)&feats, g_feats);
    cudaGetSymbolAddress((void**)&W0T, g_W0T);
    cudaGetSymbolAddress((void**)&W1T, g_W1T);
    cudaGetSymbolAddress((void**)&U1T, g_U1T);
    cudaGetSymbolAddress((void**)&U2T, g_U2T);

    cudaFuncSetAttribute(kernF, cudaFuncAttributeMaxDynamicSharedMemorySize,
                         SMEMF_BYTES);

    prepW<<<544, 256>>>(lin0_w, lin1_w, w1, w2, W0T, W1T, U1T, U2T);
    kernA<<<NPTS / 256, 256>>>(coords, emb, feats);
    kernF<<<NTILES, 512, SMEMF_BYTES>>>(feats, viewdirs, U1T, U2T, b1, b2,
                                        W0T, W1T, lin0_b, lin1_b,
                                        rgb_w, rgb_b, density, rgb);
}